// round 1
// baseline (speedup 1.0000x reference)
#include <cuda_runtime.h>
#include <cstdint>
#include <math.h>

#define BSQ 8192   // B*S tokens
#define HID 1024
#define DFF 4096
#define NE  8
#define NK  2048

// ---------------- scratch (static device globals; no allocs allowed) -------
__device__ float g_scores[BSQ * NE];                 // softmax scores [token][expert]
__device__ int   g_idx[NE * NK];                     // per-expert selected token ids
__device__ float g_gate[NE * NK];                    // per-expert gate weights
__device__ float g_h1[(size_t)NE * NK * DFF];        // 256MB intermediate H1

// ---------------- packed f32x2 helpers (sm_103a) ---------------------------
__device__ __forceinline__ unsigned long long pack2(float x, float y) {
    unsigned long long r;
    asm("mov.b64 %0, {%1, %2};" : "=l"(r) : "f"(x), "f"(y));
    return r;
}
__device__ __forceinline__ void unpack2(unsigned long long v, float& x, float& y) {
    asm("mov.b64 {%0, %1}, %2;" : "=f"(x), "=f"(y) : "l"(v));
}
__device__ __forceinline__ void ffma2(unsigned long long& d, unsigned long long a,
                                      unsigned long long b) {
    asm("fma.rn.f32x2 %0, %1, %2, %0;" : "+l"(d) : "l"(a), "l"(b));
}

// ---------------- router: logits + softmax ---------------------------------
// grid = BSQ/8 blocks, 256 threads (8 warps, 1 warp per token)
__global__ void router_kernel(const float* __restrict__ x,
                              const float* __restrict__ rw,
                              const float* __restrict__ rb) {
    __shared__ float srw[NE][HID];   // transposed: [expert][hid], conflict-free reads
    __shared__ float srb[NE];
    const int tid = threadIdx.x;
    for (int i = tid; i < HID * NE; i += 256) {
        int h = i >> 3, e = i & 7;
        srw[e][h] = rw[i];
    }
    if (tid < NE) srb[tid] = rb[tid];
    __syncthreads();

    const int w = tid >> 5, lane = tid & 31;
    const int t = blockIdx.x * 8 + w;
    const float* xr = x + (size_t)t * HID;
    float acc[NE];
#pragma unroll
    for (int e = 0; e < NE; e++) acc[e] = 0.f;
    for (int h = lane; h < HID; h += 32) {
        float xv = xr[h];
#pragma unroll
        for (int e = 0; e < NE; e++) acc[e] = fmaf(xv, srw[e][h], acc[e]);
    }
#pragma unroll
    for (int e = 0; e < NE; e++) {
#pragma unroll
        for (int off = 16; off > 0; off >>= 1)
            acc[e] += __shfl_down_sync(0xffffffffu, acc[e], off);
    }
    if (lane == 0) {
        float m = -1e30f;
#pragma unroll
        for (int e = 0; e < NE; e++) { acc[e] += srb[e]; m = fmaxf(m, acc[e]); }
        float s = 0.f;
#pragma unroll
        for (int e = 0; e < NE; e++) { acc[e] = expf(acc[e] - m); s += acc[e]; }
        float inv = 1.f / s;
#pragma unroll
        for (int e = 0; e < NE; e++) g_scores[(size_t)t * NE + e] = acc[e] * inv;
    }
}

// ---------------- top-K per expert (radix select + stable compact) ---------
// grid = NE blocks, 1024 threads; thread owns tokens [tid*8, tid*8+8)
__global__ void topk_kernel() {
    const int e = blockIdx.x;
    const int tid = threadIdx.x;
    __shared__ int sg[1024];
    __shared__ int se[1024];
    __shared__ int red;

    unsigned v[8];
#pragma unroll
    for (int j = 0; j < 8; j++) {
        int i = tid * 8 + j;
        v[j] = __float_as_uint(g_scores[(size_t)i * NE + e]);  // scores > 0: bit order == value order
    }
    if (tid == 0) red = 0;
    __syncthreads();

    // radix select K-th largest of 8192
    unsigned prefix = 0;
    int kr = NK;
    for (int bit = 31; bit >= 0; --bit) {
        unsigned want = (prefix >> bit) | 1u;
        int local = 0;
#pragma unroll
        for (int j = 0; j < 8; j++) local += ((v[j] >> bit) == want);
#pragma unroll
        for (int off = 16; off > 0; off >>= 1)
            local += __shfl_down_sync(0xffffffffu, local, off);
        if ((tid & 31) == 0) atomicAdd(&red, local);
        __syncthreads();
        int cnt = red;
        __syncthreads();
        if (tid == 0) red = 0;
        if (cnt >= kr) prefix |= (1u << bit); else kr -= cnt;
        __syncthreads();
    }
    const unsigned thr = prefix;  // K-th largest value (bit pattern)

    // stable compact: strictly-greater first, then ==thr ties in token order
    int cg = 0, ce = 0;
#pragma unroll
    for (int j = 0; j < 8; j++) { cg += (v[j] > thr); ce += (v[j] == thr); }
    sg[tid] = cg; se[tid] = ce;
    __syncthreads();
    for (int d = 1; d < 1024; d <<= 1) {   // Hillis-Steele inclusive scan
        int a = (tid >= d) ? sg[tid - d] : 0;
        int b = (tid >= d) ? se[tid - d] : 0;
        __syncthreads();
        sg[tid] += a; se[tid] += b;
        __syncthreads();
    }
    const int C = sg[1023];          // total strictly-greater (< K guaranteed)
    int pg = sg[tid] - cg;           // exclusive prefixes
    int pe = se[tid] - ce;
    const int need = NK - C;
#pragma unroll
    for (int j = 0; j < 8; j++) {
        int tok = tid * 8 + j;
        if (v[j] > thr) {
            g_idx[e * NK + pg] = tok;
            g_gate[e * NK + pg] = __uint_as_float(v[j]);
            pg++;
        } else if (v[j] == thr) {
            if (pe < need) {
                int pos = C + pe;
                g_idx[e * NK + pos] = tok;
                g_gate[e * NK + pos] = __uint_as_float(v[j]);
            }
            pe++;
        }
    }
}

// ---------------- GEMM1: H1[e] = relu(gather(x, idx[e]) @ w1[e] + b1[e]) ---
// tile 128x128, BK=8, 256 threads, packed f32x2 inner product
__global__ __launch_bounds__(256, 2)
void gemm1_kernel(const float* __restrict__ x, const float* __restrict__ w1,
                  const float* __restrict__ b1) {
    const int e  = blockIdx.z;
    const int n0 = blockIdx.x * 128;
    const int m0 = blockIdx.y * 128;
    __shared__ __align__(16) float As[8][128];
    __shared__ __align__(16) float Bs[8][128];

    const int tid  = threadIdx.x;
    const int arow = tid >> 1, aseg = tid & 1;
    const int brow = tid >> 5, bcol = (tid & 31) * 4;
    const int tok = g_idx[e * NK + m0 + arow];
    const float* aptr = x + (size_t)tok * HID + aseg * 4;
    const float* bptr = w1 + (size_t)e * HID * DFF + (size_t)brow * DFF + n0 + bcol;

    const int tx = tid & 15, ty = tid >> 4;
    unsigned long long acc[8][4];
#pragma unroll
    for (int i = 0; i < 8; i++) {
#pragma unroll
        for (int j = 0; j < 4; j++) acc[i][j] = 0ull;
    }

    float4 av = *(const float4*)aptr;
    float4 bv = *(const float4*)bptr;
    for (int k0 = 0; k0 < HID; k0 += 8) {
        As[aseg * 4 + 0][arow] = av.x;
        As[aseg * 4 + 1][arow] = av.y;
        As[aseg * 4 + 2][arow] = av.z;
        As[aseg * 4 + 3][arow] = av.w;
        *(float4*)&Bs[brow][bcol] = bv;
        __syncthreads();
        if (k0 + 8 < HID) {   // prefetch next tiles under the compute
            av = *(const float4*)(aptr + k0 + 8);
            bv = *(const float4*)(bptr + (size_t)(k0 + 8) * DFF);
        }
#pragma unroll
        for (int kk = 0; kk < 8; kk++) {
            const float4* ap4 = (const float4*)&As[kk][ty * 8];
            float4 a0 = ap4[0], a1 = ap4[1];
            const ulonglong2* bp2 = (const ulonglong2*)&Bs[kk][tx * 8];
            ulonglong2 bq0 = bp2[0], bq1 = bp2[1];
            float aa[8] = {a0.x, a0.y, a0.z, a0.w, a1.x, a1.y, a1.z, a1.w};
#pragma unroll
            for (int i = 0; i < 8; i++) {
                unsigned long long ad = pack2(aa[i], aa[i]);
                ffma2(acc[i][0], ad, bq0.x);
                ffma2(acc[i][1], ad, bq0.y);
                ffma2(acc[i][2], ad, bq1.x);
                ffma2(acc[i][3], ad, bq1.y);
            }
        }
        __syncthreads();
    }

    const int c0 = n0 + tx * 8;
    float bias[8];
    *(float4*)&bias[0] = *(const float4*)&b1[e * DFF + c0];
    *(float4*)&bias[4] = *(const float4*)&b1[e * DFF + c0 + 4];
#pragma unroll
    for (int i = 0; i < 8; i++) {
        int r = m0 + ty * 8 + i;
        float ov[8];
#pragma unroll
        for (int j = 0; j < 4; j++) {
            float lo, hi;
            unpack2(acc[i][j], lo, hi);
            ov[2 * j] = lo; ov[2 * j + 1] = hi;
        }
#pragma unroll
        for (int j = 0; j < 8; j++) ov[j] = fmaxf(ov[j] + bias[j], 0.f);
        float* dst = &g_h1[((size_t)e * NK + r) * DFF + c0];
        *(float4*)dst = *(float4*)&ov[0];
        *(float4*)(dst + 4) = *(float4*)&ov[4];
    }
}

// ---------------- GEMM2: out += gate * (H1[e] @ w2[e] + b2[e]) scatter -----
__global__ __launch_bounds__(256, 2)
void gemm2_kernel(const float* __restrict__ w2, const float* __restrict__ b2,
                  float* __restrict__ out) {
    const int e  = blockIdx.z;
    const int n0 = blockIdx.x * 128;
    const int m0 = blockIdx.y * 128;
    __shared__ __align__(16) float As[8][128];
    __shared__ __align__(16) float Bs[8][128];

    const int tid  = threadIdx.x;
    const int arow = tid >> 1, aseg = tid & 1;
    const int brow = tid >> 5, bcol = (tid & 31) * 4;
    const float* aptr = g_h1 + ((size_t)e * NK + m0 + arow) * DFF + aseg * 4;
    const float* bptr = w2 + (size_t)e * DFF * HID + (size_t)brow * HID + n0 + bcol;

    const int tx = tid & 15, ty = tid >> 4;
    unsigned long long acc[8][4];
#pragma unroll
    for (int i = 0; i < 8; i++) {
#pragma unroll
        for (int j = 0; j < 4; j++) acc[i][j] = 0ull;
    }

    float4 av = *(const float4*)aptr;
    float4 bv = *(const float4*)bptr;
    for (int k0 = 0; k0 < DFF; k0 += 8) {
        As[aseg * 4 + 0][arow] = av.x;
        As[aseg * 4 + 1][arow] = av.y;
        As[aseg * 4 + 2][arow] = av.z;
        As[aseg * 4 + 3][arow] = av.w;
        *(float4*)&Bs[brow][bcol] = bv;
        __syncthreads();
        if (k0 + 8 < DFF) {
            av = *(const float4*)(aptr + k0 + 8);
            bv = *(const float4*)(bptr + (size_t)(k0 + 8) * HID);
        }
#pragma unroll
        for (int kk = 0; kk < 8; kk++) {
            const float4* ap4 = (const float4*)&As[kk][ty * 8];
            float4 a0 = ap4[0], a1 = ap4[1];
            const ulonglong2* bp2 = (const ulonglong2*)&Bs[kk][tx * 8];
            ulonglong2 bq0 = bp2[0], bq1 = bp2[1];
            float aa[8] = {a0.x, a0.y, a0.z, a0.w, a1.x, a1.y, a1.z, a1.w};
#pragma unroll
            for (int i = 0; i < 8; i++) {
                unsigned long long ad = pack2(aa[i], aa[i]);
                ffma2(acc[i][0], ad, bq0.x);
                ffma2(acc[i][1], ad, bq0.y);
                ffma2(acc[i][2], ad, bq1.x);
                ffma2(acc[i][3], ad, bq1.y);
            }
        }
        __syncthreads();
    }

    const int c0 = n0 + tx * 8;
    float bias[8];
    *(float4*)&bias[0] = *(const float4*)&b2[e * HID + c0];
    *(float4*)&bias[4] = *(const float4*)&b2[e * HID + c0 + 4];
#pragma unroll
    for (int i = 0; i < 8; i++) {
        int r = m0 + ty * 8 + i;
        int tok = g_idx[e * NK + r];
        float gate = g_gate[e * NK + r];
        float ov[8];
#pragma unroll
        for (int j = 0; j < 4; j++) {
            float lo, hi;
            unpack2(acc[i][j], lo, hi);
            ov[2 * j] = lo; ov[2 * j + 1] = hi;
        }
        float* dst = out + (size_t)tok * HID + c0;
#pragma unroll
        for (int j = 0; j < 8; j++)
            atomicAdd(dst + j, (ov[j] + bias[j]) * gate);
    }
}

// ---------------- launch ---------------------------------------------------
extern "C" void kernel_launch(void* const* d_in, const int* in_sizes, int n_in,
                              void* d_out, int out_size) {
    const float* x  = (const float*)d_in[0];
    const float* rw = (const float*)d_in[1];
    const float* rb = (const float*)d_in[2];
    const float* w1 = (const float*)d_in[3];
    const float* b1 = (const float*)d_in[4];
    const float* w2 = (const float*)d_in[5];
    const float* b2 = (const float*)d_in[6];
    float* out = (float*)d_out;

    router_kernel<<<BSQ / 8, 256>>>(x, rw, rb);
    topk_kernel<<<NE, 1024>>>();
    cudaMemsetAsync(d_out, 0, (size_t)out_size * sizeof(float), 0);
    gemm1_kernel<<<dim3(DFF / 128, NK / 128, NE), 256>>>(x, w1, b1);
    gemm2_kernel<<<dim3(HID / 128, NK / 128, NE), 256>>>(w2, b2, out);
}

// round 3
// speedup vs baseline: 2.7927x; 2.7927x over previous
#include <cuda_runtime.h>
#include <cstdint>
#include <math.h>

#define BSQ 8192   // B*S tokens
#define HID 1024
#define DFF 4096
#define NE  8
#define NK  2048

// GEMM tiling: block 128x128x32, 8 warps of 64x32
#define BM 128
#define BN 128
#define BK 32
#define NSTAGE 4
#define ROWSTRIDE 36                               // floats; 36 % 32 == 4 -> conflict-free frags
#define TILE_FLOATS (128 * ROWSTRIDE)              // per operand per stage
#define STAGE_BYTES (2 * TILE_FLOATS * 4)          // A + B = 36864 B
#define SMEM_SZ (NSTAGE * STAGE_BYTES)             // 147456 B

// ---------------- scratch -------------------------------------------------
__device__ float g_scores[BSQ * NE];
__device__ int   g_idx[NE * NK];
__device__ float g_gate[NE * NK];
__device__ __align__(256) float g_h1[(size_t)NE * NK * DFF];   // 256MB (tf32-rounded)
__device__ __align__(256) float g_A[(size_t)NE * NK * HID];    // 64MB gathered tokens
__device__ __align__(256) float g_w1t[(size_t)NE * DFF * HID]; // w1^T (K-major)
__device__ __align__(256) float g_w2t[(size_t)NE * HID * DFF]; // w2^T (K-major)

// ---------------- helpers ---------------------------------------------------
__device__ __forceinline__ float to_tf32f(float f) {
    uint32_t u;
    asm("cvt.rna.tf32.f32 %0, %1;" : "=r"(u) : "f"(f));
    return __uint_as_float(u);
}
__device__ __forceinline__ uint32_t smem_u32(const void* p) {
    uint32_t a;
    asm("{ .reg .u64 t; cvta.to.shared.u64 t, %1; cvt.u32.u64 %0, t; }" : "=r"(a) : "l"(p));
    return a;
}
__device__ __forceinline__ void cp16(uint32_t dst, const float* src) {
    asm volatile("cp.async.cg.shared.global [%0], [%1], 16;" :: "r"(dst), "l"(src));
}
__device__ __forceinline__ void cp_commit() {
    asm volatile("cp.async.commit_group;" ::: "memory");
}
__device__ __forceinline__ void cp_wait2() {
    asm volatile("cp.async.wait_group 2;" ::: "memory");
}
__device__ __forceinline__ void mma_tf32(float* d, const uint32_t* a, const uint32_t* b) {
    asm volatile("mma.sync.aligned.m16n8k8.row.col.f32.tf32.tf32.f32 "
                 "{%0,%1,%2,%3}, {%4,%5,%6,%7}, {%8,%9}, {%0,%1,%2,%3};"
                 : "+f"(d[0]), "+f"(d[1]), "+f"(d[2]), "+f"(d[3])
                 : "r"(a[0]), "r"(a[1]), "r"(a[2]), "r"(a[3]), "r"(b[0]), "r"(b[1]));
}

// ---------------- router ---------------------------------------------------
__global__ void router_kernel(const float* __restrict__ x,
                              const float* __restrict__ rw,
                              const float* __restrict__ rb) {
    __shared__ float srw[NE][HID];
    __shared__ float srb[NE];
    const int tid = threadIdx.x;
    for (int i = tid; i < HID * NE; i += 256) {
        int h = i >> 3, e = i & 7;
        srw[e][h] = rw[i];
    }
    if (tid < NE) srb[tid] = rb[tid];
    __syncthreads();

    const int w = tid >> 5, lane = tid & 31;
    const int t = blockIdx.x * 8 + w;
    const float* xr = x + (size_t)t * HID;
    float acc[NE];
#pragma unroll
    for (int e = 0; e < NE; e++) acc[e] = 0.f;
    for (int h = lane; h < HID; h += 32) {
        float xv = xr[h];
#pragma unroll
        for (int e = 0; e < NE; e++) acc[e] = fmaf(xv, srw[e][h], acc[e]);
    }
#pragma unroll
    for (int e = 0; e < NE; e++) {
#pragma unroll
        for (int off = 16; off > 0; off >>= 1)
            acc[e] += __shfl_down_sync(0xffffffffu, acc[e], off);
    }
    if (lane == 0) {
        float m = -1e30f;
#pragma unroll
        for (int e = 0; e < NE; e++) { acc[e] += srb[e]; m = fmaxf(m, acc[e]); }
        float s = 0.f;
#pragma unroll
        for (int e = 0; e < NE; e++) { acc[e] = expf(acc[e] - m); s += acc[e]; }
        float inv = 1.f / s;
#pragma unroll
        for (int e = 0; e < NE; e++) g_scores[(size_t)t * NE + e] = acc[e] * inv;
    }
}

// ---------------- top-K per expert -----------------------------------------
__global__ void topk_kernel() {
    const int e = blockIdx.x;
    const int tid = threadIdx.x;
    __shared__ int sg[1024];
    __shared__ int se[1024];
    __shared__ int red;

    unsigned v[8];
#pragma unroll
    for (int j = 0; j < 8; j++) {
        int i = tid * 8 + j;
        v[j] = __float_as_uint(g_scores[(size_t)i * NE + e]);
    }
    if (tid == 0) red = 0;
    __syncthreads();

    unsigned prefix = 0;
    int kr = NK;
    for (int bit = 31; bit >= 0; --bit) {
        unsigned want = (prefix >> bit) | 1u;
        int local = 0;
#pragma unroll
        for (int j = 0; j < 8; j++) local += ((v[j] >> bit) == want);
#pragma unroll
        for (int off = 16; off > 0; off >>= 1)
            local += __shfl_down_sync(0xffffffffu, local, off);
        if ((tid & 31) == 0) atomicAdd(&red, local);
        __syncthreads();
        int cnt = red;
        __syncthreads();
        if (tid == 0) red = 0;
        if (cnt >= kr) prefix |= (1u << bit); else kr -= cnt;
        __syncthreads();
    }
    const unsigned thr = prefix;

    int cg = 0, ce = 0;
#pragma unroll
    for (int j = 0; j < 8; j++) { cg += (v[j] > thr); ce += (v[j] == thr); }
    sg[tid] = cg; se[tid] = ce;
    __syncthreads();
    for (int d = 1; d < 1024; d <<= 1) {
        int a = (tid >= d) ? sg[tid - d] : 0;
        int b = (tid >= d) ? se[tid - d] : 0;
        __syncthreads();
        sg[tid] += a; se[tid] += b;
        __syncthreads();
    }
    const int C = sg[1023];
    int pg = sg[tid] - cg;
    int pe = se[tid] - ce;
    const int need = NK - C;
#pragma unroll
    for (int j = 0; j < 8; j++) {
        int tok = tid * 8 + j;
        if (v[j] > thr) {
            g_idx[e * NK + pg] = tok;
            g_gate[e * NK + pg] = __uint_as_float(v[j]);
            pg++;
        } else if (v[j] == thr) {
            if (pe < need) {
                int pos = C + pe;
                g_idx[e * NK + pos] = tok;
                g_gate[e * NK + pos] = __uint_as_float(v[j]);
            }
            pe++;
        }
    }
}

// ---------------- pre-passes ------------------------------------------------
__global__ void gather_kernel(const float* __restrict__ x) {
    const int row = blockIdx.x;
    const int tok = g_idx[row];
    const float4* s = (const float4*)(x + (size_t)tok * HID);
    float4* d = (float4*)(g_A + (size_t)row * HID);
    float4 v = s[threadIdx.x];
    v.x = to_tf32f(v.x); v.y = to_tf32f(v.y);
    v.z = to_tf32f(v.z); v.w = to_tf32f(v.w);
    d[threadIdx.x] = v;
}

// per-expert transpose [R,C] -> [C,R], tf32-rounded
__global__ void transpose_kernel(const float* __restrict__ src, float* __restrict__ dst,
                                 int R, int C) {
    __shared__ float t[32][33];
    const int e = blockIdx.z;
    const float* s = src + (size_t)e * R * C;
    float* d = dst + (size_t)e * R * C;
    const int r0 = blockIdx.y * 32, c0 = blockIdx.x * 32;
#pragma unroll
    for (int i = threadIdx.y; i < 32; i += 8)
        t[i][threadIdx.x] = s[(size_t)(r0 + i) * C + c0 + threadIdx.x];
    __syncthreads();
#pragma unroll
    for (int i = threadIdx.y; i < 32; i += 8)
        d[(size_t)(c0 + i) * R + r0 + threadIdx.x] = to_tf32f(t[threadIdx.x][i]);
}

// ---------------- mma.sync tf32 mainloop -----------------------------------
// A: BM rows x K (K-contig), B: BN rows x K (K-contig). acc[4][4][4] per thread.
struct GemmCtx {
    float acc[4][4][4];
};

__device__ __forceinline__ void load_stage(uint32_t sb, int buf, int tid,
                                           const float* aG, const float* bG,
                                           int K, int k0) {
    const uint32_t base = sb + buf * STAGE_BYTES;
#pragma unroll
    for (int i = 0; i < 4; i++) {                       // A: 1024 cp16
        int id = tid + (i << 8);
        int r = id >> 3, kc = id & 7;
        cp16(base + (r * ROWSTRIDE + kc * 4) * 4, aG + (size_t)r * K + k0 + kc * 4);
    }
#pragma unroll
    for (int i = 0; i < 4; i++) {                       // B: 1024 cp16
        int id = tid + (i << 8);
        int r = id >> 3, kc = id & 7;
        cp16(base + (TILE_FLOATS + r * ROWSTRIDE + kc * 4) * 4,
             bG + (size_t)r * K + k0 + kc * 4);
    }
}

__device__ __forceinline__ void gemm_mainloop(GemmCtx& ctx, const float* smem,
                                              uint32_t sb, int tid,
                                              const float* aG, const float* bG, int K) {
    const int wid = tid >> 5, lane = tid & 31;
    const int wm = wid & 1, wn = wid >> 1;              // 2 x 4 warp grid
    const int g = lane >> 2, c = lane & 3;
    const int KT = K / BK;

#pragma unroll
    for (int mt = 0; mt < 4; mt++)
#pragma unroll
        for (int nt = 0; nt < 4; nt++)
#pragma unroll
            for (int q = 0; q < 4; q++) ctx.acc[mt][nt][q] = 0.f;

    for (int s = 0; s < NSTAGE - 1 && s < KT; s++) {
        load_stage(sb, s, tid, aG, bG, K, s * BK);
        cp_commit();
    }

    for (int k = 0; k < KT; k++) {
        const int buf = k & (NSTAGE - 1);
        cp_wait2();
        __syncthreads();

        const float* Ab = smem + (size_t)buf * (STAGE_BYTES / 4);
        const float* Bb = Ab + TILE_FLOATS;
#pragma unroll
        for (int kk = 0; kk < 4; kk++) {
            uint32_t aF[4][4], bF[4][2];
#pragma unroll
            for (int mt = 0; mt < 4; mt++) {
                const float* p = Ab + (wm * 64 + mt * 16 + g) * ROWSTRIDE + kk * 8 + c;
                aF[mt][0] = __float_as_uint(p[0]);
                aF[mt][1] = __float_as_uint(p[8 * ROWSTRIDE]);
                aF[mt][2] = __float_as_uint(p[4]);
                aF[mt][3] = __float_as_uint(p[8 * ROWSTRIDE + 4]);
            }
#pragma unroll
            for (int nt = 0; nt < 4; nt++) {
                const float* p = Bb + (wn * 32 + nt * 8 + g) * ROWSTRIDE + kk * 8 + c;
                bF[nt][0] = __float_as_uint(p[0]);
                bF[nt][1] = __float_as_uint(p[4]);
            }
#pragma unroll
            for (int mt = 0; mt < 4; mt++)
#pragma unroll
                for (int nt = 0; nt < 4; nt++)
                    mma_tf32(ctx.acc[mt][nt], aF[mt], bF[nt]);
        }
        __syncthreads();

        const int pf = k + NSTAGE - 1;
        if (pf < KT) load_stage(sb, pf & (NSTAGE - 1), tid, aG, bG, K, pf * BK);
        cp_commit();   // empty group if no prefetch: keeps wait_group 2 invariant
    }
}

// ---------------- GEMM1: g_h1 = tf32(relu(g_A @ w1t^T + b1)) ----------------
__global__ __launch_bounds__(256, 1)
void gemm1_tc(const float* __restrict__ b1) {
    extern __shared__ float smem[];
    const uint32_t sb = smem_u32(smem);
    const int tid = threadIdx.x;
    const int e = blockIdx.z, n0 = blockIdx.x * BN, m0 = blockIdx.y * BM;

    const float* aG = g_A + (size_t)(e * NK + m0) * HID;
    const float* bG = g_w1t + ((size_t)e * DFF + n0) * HID;

    GemmCtx ctx;
    gemm_mainloop(ctx, smem, sb, tid, aG, bG, HID);

    const int wid = tid >> 5, lane = tid & 31;
    const int wm = wid & 1, wn = wid >> 1;
    const int g = lane >> 2, c = lane & 3;
#pragma unroll
    for (int mt = 0; mt < 4; mt++) {
        const int r0 = m0 + wm * 64 + mt * 16 + g;
#pragma unroll
        for (int nt = 0; nt < 4; nt++) {
            const int cc = n0 + wn * 32 + nt * 8 + 2 * c;
            const float bx = b1[(size_t)e * DFF + cc];
            const float by = b1[(size_t)e * DFF + cc + 1];
            float2 v0 = make_float2(to_tf32f(fmaxf(ctx.acc[mt][nt][0] + bx, 0.f)),
                                    to_tf32f(fmaxf(ctx.acc[mt][nt][1] + by, 0.f)));
            float2 v1 = make_float2(to_tf32f(fmaxf(ctx.acc[mt][nt][2] + bx, 0.f)),
                                    to_tf32f(fmaxf(ctx.acc[mt][nt][3] + by, 0.f)));
            *(float2*)&g_h1[(size_t)(e * NK + r0) * DFF + cc] = v0;
            *(float2*)&g_h1[(size_t)(e * NK + r0 + 8) * DFF + cc] = v1;
        }
    }
}

// ---------------- GEMM2: out += gate * (g_h1 @ w2t^T + b2) ------------------
__global__ __launch_bounds__(256, 1)
void gemm2_tc(const float* __restrict__ b2, float* __restrict__ out) {
    extern __shared__ float smem[];
    const uint32_t sb = smem_u32(smem);
    const int tid = threadIdx.x;
    const int e = blockIdx.z, n0 = blockIdx.x * BN, m0 = blockIdx.y * BM;

    const float* aG = g_h1 + (size_t)(e * NK + m0) * DFF;
    const float* bG = g_w2t + ((size_t)e * HID + n0) * DFF;

    GemmCtx ctx;
    gemm_mainloop(ctx, smem, sb, tid, aG, bG, DFF);

    const int wid = tid >> 5, lane = tid & 31;
    const int wm = wid & 1, wn = wid >> 1;
    const int g = lane >> 2, c = lane & 3;
#pragma unroll
    for (int mt = 0; mt < 4; mt++) {
        const int r0 = m0 + wm * 64 + mt * 16 + g;
        const int tok0 = g_idx[e * NK + r0];
        const int tok1 = g_idx[e * NK + r0 + 8];
        const float g0 = g_gate[e * NK + r0];
        const float g1 = g_gate[e * NK + r0 + 8];
#pragma unroll
        for (int nt = 0; nt < 4; nt++) {
            const int cc = n0 + wn * 32 + nt * 8 + 2 * c;
            const float bx = b2[(size_t)e * HID + cc];
            const float by = b2[(size_t)e * HID + cc + 1];
            atomicAdd(out + (size_t)tok0 * HID + cc,     (ctx.acc[mt][nt][0] + bx) * g0);
            atomicAdd(out + (size_t)tok0 * HID + cc + 1, (ctx.acc[mt][nt][1] + by) * g0);
            atomicAdd(out + (size_t)tok1 * HID + cc,     (ctx.acc[mt][nt][2] + bx) * g1);
            atomicAdd(out + (size_t)tok1 * HID + cc + 1, (ctx.acc[mt][nt][3] + by) * g1);
        }
    }
}

// ---------------- launch ----------------------------------------------------
extern "C" void kernel_launch(void* const* d_in, const int* in_sizes, int n_in,
                              void* d_out, int out_size) {
    const float* x  = (const float*)d_in[0];
    const float* rw = (const float*)d_in[1];
    const float* rb = (const float*)d_in[2];
    const float* w1 = (const float*)d_in[3];
    const float* b1 = (const float*)d_in[4];
    const float* w2 = (const float*)d_in[5];
    const float* b2 = (const float*)d_in[6];
    float* out = (float*)d_out;

    cudaFuncSetAttribute(gemm1_tc, cudaFuncAttributeMaxDynamicSharedMemorySize, SMEM_SZ);
    cudaFuncSetAttribute(gemm2_tc, cudaFuncAttributeMaxDynamicSharedMemorySize, SMEM_SZ);

    float* w1t; cudaGetSymbolAddress((void**)&w1t, g_w1t);
    float* w2t; cudaGetSymbolAddress((void**)&w2t, g_w2t);

    transpose_kernel<<<dim3(DFF / 32, HID / 32, NE), dim3(32, 8)>>>(w1, w1t, HID, DFF);
    transpose_kernel<<<dim3(HID / 32, DFF / 32, NE), dim3(32, 8)>>>(w2, w2t, DFF, HID);
    router_kernel<<<BSQ / 8, 256>>>(x, rw, rb);
    topk_kernel<<<NE, 1024>>>();
    gather_kernel<<<NE * NK, 256>>>(x);
    cudaMemsetAsync(d_out, 0, (size_t)out_size * sizeof(float), 0);
    gemm1_tc<<<dim3(DFF / BN, NK / BM, NE), 256, SMEM_SZ>>>(b1);
    gemm2_tc<<<dim3(HID / BN, NK / BM, NE), 256, SMEM_SZ>>>(b2, out);
}

// round 4
// speedup vs baseline: 3.0749x; 1.1011x over previous
#include <cuda_runtime.h>
#include <cstdint>
#include <math.h>

#define BSQ 8192   // B*S tokens
#define HID 1024
#define DFF 4096
#define NE  8
#define NK  2048

// GEMM tiling: CTA 128x256x32, 8 warps of 64x64
#define BM 128
#define BN 256
#define BK 32
#define NSTAGE 3
#define RSA 36                          // A row stride (floats); 36%32==4 -> conflict-free frags
#define RSB 264                         // B row stride (floats); 264%32==8 -> conflict-free frags
#define A_FLOATS (BM * RSA)             // 4608
#define B_FLOATS (BK * RSB)             // 8448
#define STAGE_FLOATS (A_FLOATS + B_FLOATS)
#define SMEM_SZ (NSTAGE * STAGE_FLOATS * 4)   // 156672 B

// ---------------- scratch -------------------------------------------------
__device__ float g_scores[BSQ * NE];
__device__ int   g_idx[NE * NK];
__device__ float g_gate[NE * NK];
__device__ __align__(256) float g_h1[(size_t)NE * NK * DFF];   // 256MB (tf32-rounded)

// ---------------- helpers ---------------------------------------------------
__device__ __forceinline__ float to_tf32f(float f) {
    uint32_t u;
    asm("cvt.rna.tf32.f32 %0, %1;" : "=r"(u) : "f"(f));
    return __uint_as_float(u);
}
__device__ __forceinline__ uint32_t to_tf32u(float f) {
    uint32_t u;
    asm("cvt.rna.tf32.f32 %0, %1;" : "=r"(u) : "f"(f));
    return u;
}
__device__ __forceinline__ uint32_t smem_u32(const void* p) {
    uint32_t a;
    asm("{ .reg .u64 t; cvta.to.shared.u64 t, %1; cvt.u32.u64 %0, t; }" : "=r"(a) : "l"(p));
    return a;
}
__device__ __forceinline__ void cp16(uint32_t dst, const float* src) {
    asm volatile("cp.async.cg.shared.global [%0], [%1], 16;" :: "r"(dst), "l"(src));
}
__device__ __forceinline__ void cp_commit() {
    asm volatile("cp.async.commit_group;" ::: "memory");
}
__device__ __forceinline__ void cp_wait1() {
    asm volatile("cp.async.wait_group 1;" ::: "memory");
}
__device__ __forceinline__ void mma_tf32(float* d, const uint32_t* a, const uint32_t* b) {
    asm volatile("mma.sync.aligned.m16n8k8.row.col.f32.tf32.tf32.f32 "
                 "{%0,%1,%2,%3}, {%4,%5,%6,%7}, {%8,%9}, {%0,%1,%2,%3};"
                 : "+f"(d[0]), "+f"(d[1]), "+f"(d[2]), "+f"(d[3])
                 : "r"(a[0]), "r"(a[1]), "r"(a[2]), "r"(a[3]), "r"(b[0]), "r"(b[1]));
}

// ---------------- router ---------------------------------------------------
__global__ void router_kernel(const float* __restrict__ x,
                              const float* __restrict__ rw,
                              const float* __restrict__ rb) {
    __shared__ float srw[NE][HID];
    __shared__ float srb[NE];
    const int tid = threadIdx.x;
    for (int i = tid; i < HID * NE; i += 256) {
        int h = i >> 3, e = i & 7;
        srw[e][h] = rw[i];
    }
    if (tid < NE) srb[tid] = rb[tid];
    __syncthreads();

    const int w = tid >> 5, lane = tid & 31;
    const int t = blockIdx.x * 8 + w;
    const float* xr = x + (size_t)t * HID;
    float acc[NE];
#pragma unroll
    for (int e = 0; e < NE; e++) acc[e] = 0.f;
    for (int h = lane; h < HID; h += 32) {
        float xv = xr[h];
#pragma unroll
        for (int e = 0; e < NE; e++) acc[e] = fmaf(xv, srw[e][h], acc[e]);
    }
#pragma unroll
    for (int e = 0; e < NE; e++) {
#pragma unroll
        for (int off = 16; off > 0; off >>= 1)
            acc[e] += __shfl_down_sync(0xffffffffu, acc[e], off);
    }
    if (lane == 0) {
        float m = -1e30f;
#pragma unroll
        for (int e = 0; e < NE; e++) { acc[e] += srb[e]; m = fmaxf(m, acc[e]); }
        float s = 0.f;
#pragma unroll
        for (int e = 0; e < NE; e++) { acc[e] = expf(acc[e] - m); s += acc[e]; }
        float inv = 1.f / s;
#pragma unroll
        for (int e = 0; e < NE; e++) g_scores[(size_t)t * NE + e] = acc[e] * inv;
    }
}

// ---------------- top-K per expert -----------------------------------------
__global__ void topk_kernel() {
    const int e = blockIdx.x;
    const int tid = threadIdx.x;
    __shared__ int sg[1024];
    __shared__ int se[1024];
    __shared__ int red;

    unsigned v[8];
#pragma unroll
    for (int j = 0; j < 8; j++) {
        int i = tid * 8 + j;
        v[j] = __float_as_uint(g_scores[(size_t)i * NE + e]);
    }
    if (tid == 0) red = 0;
    __syncthreads();

    unsigned prefix = 0;
    int kr = NK;
    for (int bit = 31; bit >= 0; --bit) {
        unsigned want = (prefix >> bit) | 1u;
        int local = 0;
#pragma unroll
        for (int j = 0; j < 8; j++) local += ((v[j] >> bit) == want);
#pragma unroll
        for (int off = 16; off > 0; off >>= 1)
            local += __shfl_down_sync(0xffffffffu, local, off);
        if ((tid & 31) == 0) atomicAdd(&red, local);
        __syncthreads();
        int cnt = red;
        __syncthreads();
        if (tid == 0) red = 0;
        if (cnt >= kr) prefix |= (1u << bit); else kr -= cnt;
        __syncthreads();
    }
    const unsigned thr = prefix;

    int cg = 0, ce = 0;
#pragma unroll
    for (int j = 0; j < 8; j++) { cg += (v[j] > thr); ce += (v[j] == thr); }
    sg[tid] = cg; se[tid] = ce;
    __syncthreads();
    for (int d = 1; d < 1024; d <<= 1) {
        int a = (tid >= d) ? sg[tid - d] : 0;
        int b = (tid >= d) ? se[tid - d] : 0;
        __syncthreads();
        sg[tid] += a; se[tid] += b;
        __syncthreads();
    }
    const int C = sg[1023];
    int pg = sg[tid] - cg;
    int pe = se[tid] - ce;
    const int need = NK - C;
#pragma unroll
    for (int j = 0; j < 8; j++) {
        int tok = tid * 8 + j;
        if (v[j] > thr) {
            g_idx[e * NK + pg] = tok;
            g_gate[e * NK + pg] = __uint_as_float(v[j]);
            pg++;
        } else if (v[j] == thr) {
            if (pe < need) {
                int pos = C + pe;
                g_idx[e * NK + pos] = tok;
                g_gate[e * NK + pos] = __uint_as_float(v[j]);
            }
            pe++;
        }
    }
}

// ---------------- mma.sync tf32 mainloop -----------------------------------
// A rows via sptr[] (K-contig rows), B row-major [K][Nld] at bG (N-contig rows).
// Warp tile 64x64: acc[4][8][4].
__device__ __forceinline__ void load_stage(uint32_t sb, int buf, int tid,
                                           const float* const* sptr,
                                           const float* bG, int Nld, int k0) {
    const uint32_t baseA = sb + buf * STAGE_FLOATS * 4;
    const uint32_t baseB = baseA + A_FLOATS * 4;
#pragma unroll
    for (int i = 0; i < 4; i++) {                       // A: 1024 cp16 (128 x 32)
        int id = tid + (i << 8);
        int r = id >> 3, kc = id & 7;
        cp16(baseA + (r * RSA + kc * 4) * 4, sptr[r] + k0 + kc * 4);
    }
#pragma unroll
    for (int i = 0; i < 8; i++) {                       // B: 2048 cp16 (32 x 256)
        int id = tid + (i << 8);
        int kr = id >> 6, nc = id & 63;
        cp16(baseB + (kr * RSB + nc * 4) * 4, bG + (size_t)(k0 + kr) * Nld + nc * 4);
    }
}

__device__ __forceinline__ void gemm_mainloop(float acc[4][8][4], const float* smem,
                                              uint32_t sb, int tid,
                                              const float* const* sptr,
                                              const float* bG, int Nld, int K) {
    const int wid = tid >> 5, lane = tid & 31;
    const int wm = wid & 1, wn = wid >> 1;              // 2 x 4 warp grid, 64x64 tiles
    const int g = lane >> 2, c = lane & 3;
    const int KT = K / BK;

#pragma unroll
    for (int mt = 0; mt < 4; mt++)
#pragma unroll
        for (int nt = 0; nt < 8; nt++)
#pragma unroll
            for (int q = 0; q < 4; q++) acc[mt][nt][q] = 0.f;

    for (int s = 0; s < NSTAGE - 1; s++) {
        load_stage(sb, s, tid, sptr, bG, Nld, s * BK);
        cp_commit();
    }

    for (int k = 0; k < KT; k++) {
        const int buf = (k % NSTAGE);
        cp_wait1();
        __syncthreads();

        const float* Ab = smem + (size_t)buf * STAGE_FLOATS;
        const float* Bb = Ab + A_FLOATS;
#pragma unroll
        for (int kk = 0; kk < 4; kk++) {
            uint32_t aF[4][4], bF[8][2];
#pragma unroll
            for (int mt = 0; mt < 4; mt++) {
                const float* p = Ab + (wm * 64 + mt * 16 + g) * RSA + kk * 8 + c;
                aF[mt][0] = to_tf32u(p[0]);
                aF[mt][1] = to_tf32u(p[8 * RSA]);
                aF[mt][2] = to_tf32u(p[4]);
                aF[mt][3] = to_tf32u(p[8 * RSA + 4]);
            }
#pragma unroll
            for (int nt = 0; nt < 8; nt++) {
                const float* q = Bb + (kk * 8 + c) * RSB + wn * 64 + nt * 8 + g;
                bF[nt][0] = to_tf32u(q[0]);
                bF[nt][1] = to_tf32u(q[4 * RSB]);
            }
#pragma unroll
            for (int mt = 0; mt < 4; mt++)
#pragma unroll
                for (int nt = 0; nt < 8; nt++)
                    mma_tf32(acc[mt][nt], aF[mt], bF[nt]);
        }
        __syncthreads();

        const int pf = k + NSTAGE - 1;
        if (pf < KT) load_stage(sb, pf % NSTAGE, tid, sptr, bG, Nld, pf * BK);
        cp_commit();   // empty group when no prefetch keeps wait_group invariant
    }
}

// ---------------- GEMM1: g_h1 = tf32(relu(gather(x) @ w1 + b1)) -------------
__global__ __launch_bounds__(256, 1)
void gemm1_tc(const float* __restrict__ x, const float* __restrict__ w1,
              const float* __restrict__ b1) {
    extern __shared__ float smem[];
    __shared__ const float* sptr[BM];
    const uint32_t sb = smem_u32(smem);
    const int tid = threadIdx.x;
    const int e = blockIdx.z, n0 = blockIdx.x * BN, m0 = blockIdx.y * BM;

    if (tid < BM) {
        int tok = g_idx[e * NK + m0 + tid];
        sptr[tid] = x + (size_t)tok * HID;
    }
    __syncthreads();

    const float* bG = w1 + (size_t)e * HID * DFF + n0;
    float acc[4][8][4];
    gemm_mainloop(acc, smem, sb, tid, sptr, bG, DFF, HID);

    const int wid = tid >> 5, lane = tid & 31;
    const int wm = wid & 1, wn = wid >> 1;
    const int g = lane >> 2, c = lane & 3;
#pragma unroll
    for (int mt = 0; mt < 4; mt++) {
        const int r0 = m0 + wm * 64 + mt * 16 + g;
#pragma unroll
        for (int nt = 0; nt < 8; nt++) {
            const int cc = n0 + wn * 64 + nt * 8 + 2 * c;
            const float bx = b1[(size_t)e * DFF + cc];
            const float by = b1[(size_t)e * DFF + cc + 1];
            float2 v0 = make_float2(to_tf32f(fmaxf(acc[mt][nt][0] + bx, 0.f)),
                                    to_tf32f(fmaxf(acc[mt][nt][1] + by, 0.f)));
            float2 v1 = make_float2(to_tf32f(fmaxf(acc[mt][nt][2] + bx, 0.f)),
                                    to_tf32f(fmaxf(acc[mt][nt][3] + by, 0.f)));
            *(float2*)&g_h1[(size_t)(e * NK + r0) * DFF + cc] = v0;
            *(float2*)&g_h1[(size_t)(e * NK + r0 + 8) * DFF + cc] = v1;
        }
    }
}

// ---------------- GEMM2: out += gate * (g_h1 @ w2 + b2) ---------------------
__global__ __launch_bounds__(256, 1)
void gemm2_tc(const float* __restrict__ w2, const float* __restrict__ b2,
              float* __restrict__ out) {
    extern __shared__ float smem[];
    __shared__ const float* sptr[BM];
    const uint32_t sb = smem_u32(smem);
    const int tid = threadIdx.x;
    const int e = blockIdx.z, n0 = blockIdx.x * BN, m0 = blockIdx.y * BM;

    if (tid < BM)
        sptr[tid] = g_h1 + (size_t)(e * NK + m0 + tid) * DFF;
    __syncthreads();

    const float* bG = w2 + (size_t)e * DFF * HID + n0;
    float acc[4][8][4];
    gemm_mainloop(acc, smem, sb, tid, sptr, bG, HID, DFF);

    const int wid = tid >> 5, lane = tid & 31;
    const int wm = wid & 1, wn = wid >> 1;
    const int g = lane >> 2, c = lane & 3;
#pragma unroll
    for (int mt = 0; mt < 4; mt++) {
        const int r0 = m0 + wm * 64 + mt * 16 + g;
        const int tok0 = g_idx[e * NK + r0];
        const int tok1 = g_idx[e * NK + r0 + 8];
        const float g0 = g_gate[e * NK + r0];
        const float g1 = g_gate[e * NK + r0 + 8];
#pragma unroll
        for (int nt = 0; nt < 8; nt++) {
            const int cc = n0 + wn * 64 + nt * 8 + 2 * c;
            const float bx = b2[(size_t)e * HID + cc];
            const float by = b2[(size_t)e * HID + cc + 1];
            atomicAdd(out + (size_t)tok0 * HID + cc,     (acc[mt][nt][0] + bx) * g0);
            atomicAdd(out + (size_t)tok0 * HID + cc + 1, (acc[mt][nt][1] + by) * g0);
            atomicAdd(out + (size_t)tok1 * HID + cc,     (acc[mt][nt][2] + bx) * g1);
            atomicAdd(out + (size_t)tok1 * HID + cc + 1, (acc[mt][nt][3] + by) * g1);
        }
    }
}

// ---------------- launch ----------------------------------------------------
extern "C" void kernel_launch(void* const* d_in, const int* in_sizes, int n_in,
                              void* d_out, int out_size) {
    const float* x  = (const float*)d_in[0];
    const float* rw = (const float*)d_in[1];
    const float* rb = (const float*)d_in[2];
    const float* w1 = (const float*)d_in[3];
    const float* b1 = (const float*)d_in[4];
    const float* w2 = (const float*)d_in[5];
    const float* b2 = (const float*)d_in[6];
    float* out = (float*)d_out;

    cudaFuncSetAttribute(gemm1_tc, cudaFuncAttributeMaxDynamicSharedMemorySize, SMEM_SZ);
    cudaFuncSetAttribute(gemm2_tc, cudaFuncAttributeMaxDynamicSharedMemorySize, SMEM_SZ);

    router_kernel<<<BSQ / 8, 256>>>(x, rw, rb);
    topk_kernel<<<NE, 1024>>>();
    cudaMemsetAsync(d_out, 0, (size_t)out_size * sizeof(float), 0);
    gemm1_tc<<<dim3(DFF / BN, NK / BM, NE), 256, SMEM_SZ>>>(x, w1, b1);
    gemm2_tc<<<dim3(HID / BN, NK / BM, NE), 256, SMEM_SZ>>>(w2, b2, out);
}

// round 5
// speedup vs baseline: 3.2225x; 1.0480x over previous
#include <cuda_runtime.h>
#include <cstdint>
#include <math.h>

#define BSQ 8192   // B*S tokens
#define HID 1024
#define DFF 4096
#define NE  8
#define NK  2048

// GEMM tiling: CTA 128x256x32, 8 warps of 64x64
#define BM 128
#define BN 256
#define BK 32
#define NSTAGE 3
#define RSA 36                          // A row stride (floats); 36%32==4 -> conflict-free frags
#define RSB 264                         // B row stride (floats); 264%32==8 -> conflict-free frags
#define A_FLOATS (BM * RSA)             // 4608
#define B_FLOATS (BK * RSB)             // 8448
#define STAGE_FLOATS (A_FLOATS + B_FLOATS)
#define SMEM_SZ (NSTAGE * STAGE_FLOATS * 4)   // 156672 B

// ---------------- scratch -------------------------------------------------
__device__ float g_scores[BSQ * NE];
__device__ int   g_idx[NE * NK];
__device__ float g_gate[NE * NK];
__device__ __align__(256) float g_h1[(size_t)NE * NK * DFF];    // 256MB (tf32-rounded)
__device__ __align__(256) float g_A[(size_t)NE * NK * HID];     // 64MB rounded gathered tokens
__device__ __align__(256) float g_w1r[(size_t)NE * HID * DFF];  // 128MB rounded w1
__device__ __align__(256) float g_w2r[(size_t)NE * DFF * HID];  // 128MB rounded w2

// ---------------- helpers ---------------------------------------------------
__device__ __forceinline__ float to_tf32f(float f) {
    uint32_t u;
    asm("cvt.rna.tf32.f32 %0, %1;" : "=r"(u) : "f"(f));
    return __uint_as_float(u);
}
__device__ __forceinline__ uint32_t smem_u32(const void* p) {
    uint32_t a;
    asm("{ .reg .u64 t; cvta.to.shared.u64 t, %1; cvt.u32.u64 %0, t; }" : "=r"(a) : "l"(p));
    return a;
}
__device__ __forceinline__ void cp16(uint32_t dst, const float* src) {
    asm volatile("cp.async.cg.shared.global [%0], [%1], 16;" :: "r"(dst), "l"(src));
}
__device__ __forceinline__ void cp_commit() {
    asm volatile("cp.async.commit_group;" ::: "memory");
}
__device__ __forceinline__ void cp_wait1() {
    asm volatile("cp.async.wait_group 1;" ::: "memory");
}
__device__ __forceinline__ void mma_tf32(float* d, const uint32_t* a, const uint32_t* b) {
    asm volatile("mma.sync.aligned.m16n8k8.row.col.f32.tf32.tf32.f32 "
                 "{%0,%1,%2,%3}, {%4,%5,%6,%7}, {%8,%9}, {%0,%1,%2,%3};"
                 : "+f"(d[0]), "+f"(d[1]), "+f"(d[2]), "+f"(d[3])
                 : "r"(a[0]), "r"(a[1]), "r"(a[2]), "r"(a[3]), "r"(b[0]), "r"(b[1]));
}

// ---------------- router ---------------------------------------------------
__global__ void router_kernel(const float* __restrict__ x,
                              const float* __restrict__ rw,
                              const float* __restrict__ rb) {
    __shared__ float srw[NE][HID];
    __shared__ float srb[NE];
    const int tid = threadIdx.x;
    for (int i = tid; i < HID * NE; i += 256) {
        int h = i >> 3, e = i & 7;
        srw[e][h] = rw[i];
    }
    if (tid < NE) srb[tid] = rb[tid];
    __syncthreads();

    const int w = tid >> 5, lane = tid & 31;
    const int t = blockIdx.x * 8 + w;
    const float* xr = x + (size_t)t * HID;
    float acc[NE];
#pragma unroll
    for (int e = 0; e < NE; e++) acc[e] = 0.f;
    for (int h = lane; h < HID; h += 32) {
        float xv = xr[h];
#pragma unroll
        for (int e = 0; e < NE; e++) acc[e] = fmaf(xv, srw[e][h], acc[e]);
    }
#pragma unroll
    for (int e = 0; e < NE; e++) {
#pragma unroll
        for (int off = 16; off > 0; off >>= 1)
            acc[e] += __shfl_down_sync(0xffffffffu, acc[e], off);
    }
    if (lane == 0) {
        float m = -1e30f;
#pragma unroll
        for (int e = 0; e < NE; e++) { acc[e] += srb[e]; m = fmaxf(m, acc[e]); }
        float s = 0.f;
#pragma unroll
        for (int e = 0; e < NE; e++) { acc[e] = expf(acc[e] - m); s += acc[e]; }
        float inv = 1.f / s;
#pragma unroll
        for (int e = 0; e < NE; e++) g_scores[(size_t)t * NE + e] = acc[e] * inv;
    }
}

// ---------------- top-K per expert -----------------------------------------
__global__ void topk_kernel() {
    const int e = blockIdx.x;
    const int tid = threadIdx.x;
    __shared__ int sg[1024];
    __shared__ int se[1024];
    __shared__ int red;

    unsigned v[8];
#pragma unroll
    for (int j = 0; j < 8; j++) {
        int i = tid * 8 + j;
        v[j] = __float_as_uint(g_scores[(size_t)i * NE + e]);
    }
    if (tid == 0) red = 0;
    __syncthreads();

    unsigned prefix = 0;
    int kr = NK;
    for (int bit = 31; bit >= 0; --bit) {
        unsigned want = (prefix >> bit) | 1u;
        int local = 0;
#pragma unroll
        for (int j = 0; j < 8; j++) local += ((v[j] >> bit) == want);
#pragma unroll
        for (int off = 16; off > 0; off >>= 1)
            local += __shfl_down_sync(0xffffffffu, local, off);
        if ((tid & 31) == 0) atomicAdd(&red, local);
        __syncthreads();
        int cnt = red;
        __syncthreads();
        if (tid == 0) red = 0;
        if (cnt >= kr) prefix |= (1u << bit); else kr -= cnt;
        __syncthreads();
    }
    const unsigned thr = prefix;

    int cg = 0, ce = 0;
#pragma unroll
    for (int j = 0; j < 8; j++) { cg += (v[j] > thr); ce += (v[j] == thr); }
    sg[tid] = cg; se[tid] = ce;
    __syncthreads();
    for (int d = 1; d < 1024; d <<= 1) {
        int a = (tid >= d) ? sg[tid - d] : 0;
        int b = (tid >= d) ? se[tid - d] : 0;
        __syncthreads();
        sg[tid] += a; se[tid] += b;
        __syncthreads();
    }
    const int C = sg[1023];
    int pg = sg[tid] - cg;
    int pe = se[tid] - ce;
    const int need = NK - C;
#pragma unroll
    for (int j = 0; j < 8; j++) {
        int tok = tid * 8 + j;
        if (v[j] > thr) {
            g_idx[e * NK + pg] = tok;
            g_gate[e * NK + pg] = __uint_as_float(v[j]);
            pg++;
        } else if (v[j] == thr) {
            if (pe < need) {
                int pos = C + pe;
                g_idx[e * NK + pos] = tok;
                g_gate[e * NK + pos] = __uint_as_float(v[j]);
            }
            pe++;
        }
    }
}

// ---------------- pre-passes ------------------------------------------------
// rounded gather: g_A[row] = tf32(x[g_idx[row]])
__global__ void gather_kernel(const float* __restrict__ x) {
    const int row = blockIdx.x;
    const int tok = g_idx[row];
    const float4* s = (const float4*)(x + (size_t)tok * HID);
    float4* d = (float4*)(g_A + (size_t)row * HID);
    float4 v = s[threadIdx.x];
    v.x = to_tf32f(v.x); v.y = to_tf32f(v.y);
    v.z = to_tf32f(v.z); v.w = to_tf32f(v.w);
    d[threadIdx.x] = v;
}

// elementwise tf32 rounding of both weight tensors (float4-vectorized)
__global__ void round_kernel(const float* __restrict__ w1, const float* __restrict__ w2) {
    const size_t n4 = (size_t)NE * HID * DFF / 4;
    const size_t stride = (size_t)gridDim.x * blockDim.x;
    for (size_t i = (size_t)blockIdx.x * blockDim.x + threadIdx.x; i < n4; i += stride) {
        float4 a = ((const float4*)w1)[i];
        a.x = to_tf32f(a.x); a.y = to_tf32f(a.y);
        a.z = to_tf32f(a.z); a.w = to_tf32f(a.w);
        ((float4*)g_w1r)[i] = a;
        float4 b = ((const float4*)w2)[i];
        b.x = to_tf32f(b.x); b.y = to_tf32f(b.y);
        b.z = to_tf32f(b.z); b.w = to_tf32f(b.w);
        ((float4*)g_w2r)[i] = b;
    }
}

// ---------------- mma.sync tf32 mainloop -----------------------------------
// A: BM rows x K (K-contig) at aG; B row-major [K][Nld] at bG. No cvts inside.
__device__ __forceinline__ void load_stage(uint32_t sb, int buf, int tid,
                                           const float* aG, int K,
                                           const float* bG, int Nld, int k0) {
    const uint32_t baseA = sb + buf * STAGE_FLOATS * 4;
    const uint32_t baseB = baseA + A_FLOATS * 4;
#pragma unroll
    for (int i = 0; i < 4; i++) {                       // A: 1024 cp16 (128 x 32)
        int id = tid + (i << 8);
        int r = id >> 3, kc = id & 7;
        cp16(baseA + (r * RSA + kc * 4) * 4, aG + (size_t)r * K + k0 + kc * 4);
    }
#pragma unroll
    for (int i = 0; i < 8; i++) {                       // B: 2048 cp16 (32 x 256)
        int id = tid + (i << 8);
        int kr = id >> 6, nc = id & 63;
        cp16(baseB + (kr * RSB + nc * 4) * 4, bG + (size_t)(k0 + kr) * Nld + nc * 4);
    }
}

__device__ __forceinline__ void gemm_mainloop(float acc[4][8][4], const float* smem,
                                              uint32_t sb, int tid,
                                              const float* aG,
                                              const float* bG, int Nld, int K) {
    const int wid = tid >> 5, lane = tid & 31;
    const int wm = wid & 1, wn = wid >> 1;              // 2 x 4 warp grid, 64x64 tiles
    const int g = lane >> 2, c = lane & 3;
    const int KT = K / BK;
    const int aOff = (wm * 64 + g) * RSA + c;           // hoisted fragment bases
    const int bOff = c * RSB + wn * 64 + g;

#pragma unroll
    for (int mt = 0; mt < 4; mt++)
#pragma unroll
        for (int nt = 0; nt < 8; nt++)
#pragma unroll
            for (int q = 0; q < 4; q++) acc[mt][nt][q] = 0.f;

    for (int s = 0; s < NSTAGE - 1; s++) {
        load_stage(sb, s, tid, aG, K, bG, Nld, s * BK);
        cp_commit();
    }

    for (int k = 0; k < KT; k++) {
        const int buf = (k % NSTAGE);
        cp_wait1();
        __syncthreads();

        const uint32_t* Ab = (const uint32_t*)(smem + (size_t)buf * STAGE_FLOATS) + aOff;
        const uint32_t* Bb = (const uint32_t*)(smem + (size_t)buf * STAGE_FLOATS + A_FLOATS) + bOff;
#pragma unroll
        for (int kk = 0; kk < 4; kk++) {
            uint32_t aF[4][4], bF[8][2];
#pragma unroll
            for (int mt = 0; mt < 4; mt++) {
                const uint32_t* p = Ab + mt * 16 * RSA + kk * 8;
                aF[mt][0] = p[0];
                aF[mt][1] = p[8 * RSA];
                aF[mt][2] = p[4];
                aF[mt][3] = p[8 * RSA + 4];
            }
#pragma unroll
            for (int nt = 0; nt < 8; nt++) {
                const uint32_t* q = Bb + kk * 8 * RSB + nt * 8;
                bF[nt][0] = q[0];
                bF[nt][1] = q[4 * RSB];
            }
#pragma unroll
            for (int mt = 0; mt < 4; mt++)
#pragma unroll
                for (int nt = 0; nt < 8; nt++)
                    mma_tf32(acc[mt][nt], aF[mt], bF[nt]);
        }
        __syncthreads();

        const int pf = k + NSTAGE - 1;
        if (pf < KT) load_stage(sb, pf % NSTAGE, tid, aG, K, bG, Nld, pf * BK);
        cp_commit();   // empty group when no prefetch keeps wait_group invariant
    }
}

// ---------------- GEMM1: g_h1 = tf32(relu(g_A @ w1r + b1)) ------------------
__global__ __launch_bounds__(256, 1)
void gemm1_tc(const float* __restrict__ b1) {
    extern __shared__ float smem[];
    const uint32_t sb = smem_u32(smem);
    const int tid = threadIdx.x;
    const int e = blockIdx.z, n0 = blockIdx.x * BN, m0 = blockIdx.y * BM;

    const float* aG = g_A + (size_t)(e * NK + m0) * HID;
    const float* bG = g_w1r + (size_t)e * HID * DFF + n0;
    float acc[4][8][4];
    gemm_mainloop(acc, smem, sb, tid, aG, bG, DFF, HID);

    const int wid = tid >> 5, lane = tid & 31;
    const int wm = wid & 1, wn = wid >> 1;
    const int g = lane >> 2, c = lane & 3;
#pragma unroll
    for (int mt = 0; mt < 4; mt++) {
        const int r0 = m0 + wm * 64 + mt * 16 + g;
#pragma unroll
        for (int nt = 0; nt < 8; nt++) {
            const int cc = n0 + wn * 64 + nt * 8 + 2 * c;
            const float bx = b1[(size_t)e * DFF + cc];
            const float by = b1[(size_t)e * DFF + cc + 1];
            float2 v0 = make_float2(to_tf32f(fmaxf(acc[mt][nt][0] + bx, 0.f)),
                                    to_tf32f(fmaxf(acc[mt][nt][1] + by, 0.f)));
            float2 v1 = make_float2(to_tf32f(fmaxf(acc[mt][nt][2] + bx, 0.f)),
                                    to_tf32f(fmaxf(acc[mt][nt][3] + by, 0.f)));
            *(float2*)&g_h1[(size_t)(e * NK + r0) * DFF + cc] = v0;
            *(float2*)&g_h1[(size_t)(e * NK + r0 + 8) * DFF + cc] = v1;
        }
    }
}

// ---------------- GEMM2: out += gate * (g_h1 @ w2r + b2) --------------------
__global__ __launch_bounds__(256, 1)
void gemm2_tc(const float* __restrict__ b2, float* __restrict__ out) {
    extern __shared__ float smem[];
    const uint32_t sb = smem_u32(smem);
    const int tid = threadIdx.x;
    const int e = blockIdx.z, n0 = blockIdx.x * BN, m0 = blockIdx.y * BM;

    const float* aG = g_h1 + (size_t)(e * NK + m0) * DFF;
    const float* bG = g_w2r + (size_t)e * DFF * HID + n0;
    float acc[4][8][4];
    gemm_mainloop(acc, smem, sb, tid, aG, bG, HID, DFF);

    const int wid = tid >> 5, lane = tid & 31;
    const int wm = wid & 1, wn = wid >> 1;
    const int g = lane >> 2, c = lane & 3;
#pragma unroll
    for (int mt = 0; mt < 4; mt++) {
        const int r0 = m0 + wm * 64 + mt * 16 + g;
        const int tok0 = g_idx[e * NK + r0];
        const int tok1 = g_idx[e * NK + r0 + 8];
        const float g0 = g_gate[e * NK + r0];
        const float g1 = g_gate[e * NK + r0 + 8];
#pragma unroll
        for (int nt = 0; nt < 8; nt++) {
            const int cc = n0 + wn * 64 + nt * 8 + 2 * c;
            const float bx = b2[(size_t)e * HID + cc];
            const float by = b2[(size_t)e * HID + cc + 1];
            atomicAdd(out + (size_t)tok0 * HID + cc,     (acc[mt][nt][0] + bx) * g0);
            atomicAdd(out + (size_t)tok0 * HID + cc + 1, (acc[mt][nt][1] + by) * g0);
            atomicAdd(out + (size_t)tok1 * HID + cc,     (acc[mt][nt][2] + bx) * g1);
            atomicAdd(out + (size_t)tok1 * HID + cc + 1, (acc[mt][nt][3] + by) * g1);
        }
    }
}

// ---------------- launch ----------------------------------------------------
extern "C" void kernel_launch(void* const* d_in, const int* in_sizes, int n_in,
                              void* d_out, int out_size) {
    const float* x  = (const float*)d_in[0];
    const float* rw = (const float*)d_in[1];
    const float* rb = (const float*)d_in[2];
    const float* w1 = (const float*)d_in[3];
    const float* b1 = (const float*)d_in[4];
    const float* w2 = (const float*)d_in[5];
    const float* b2 = (const float*)d_in[6];
    float* out = (float*)d_out;

    cudaFuncSetAttribute(gemm1_tc, cudaFuncAttributeMaxDynamicSharedMemorySize, SMEM_SZ);
    cudaFuncSetAttribute(gemm2_tc, cudaFuncAttributeMaxDynamicSharedMemorySize, SMEM_SZ);

    round_kernel<<<2048, 256>>>(w1, w2);
    router_kernel<<<BSQ / 8, 256>>>(x, rw, rb);
    topk_kernel<<<NE, 1024>>>();
    gather_kernel<<<NE * NK, 256>>>(x);
    cudaMemsetAsync(d_out, 0, (size_t)out_size * sizeof(float), 0);
    gemm1_tc<<<dim3(DFF / BN, NK / BM, NE), 256, SMEM_SZ>>>(b1);
    gemm2_tc<<<dim3(HID / BN, NK / BM, NE), 256, SMEM_SZ>>>(b2, out);
}

// round 6
// speedup vs baseline: 3.5385x; 1.0981x over previous
#include <cuda_runtime.h>
#include <cuda_fp16.h>
#include <cstdint>
#include <math.h>

#define BSQ 8192   // B*S tokens
#define HID 1024
#define DFF 4096
#define NE  8
#define NK  2048

// GEMM tiling: CTA 128x256x32, 8 warps of 64x64, fp16 m16n8k16
#define BM 128
#define BN 256
#define BK 32
#define NSTAGE 4
#define RSA 40                           // A row stride (halves): 80B rows, ldmatrix conflict-free
#define RSB 264                          // B row stride (halves): 528B rows, conflict-free
#define A_BYTES_ST (BM * RSA * 2)        // 10240
#define B_BYTES_ST (BK * RSB * 2)        // 16896
#define STAGE_BYTES (A_BYTES_ST + B_BYTES_ST)   // 27136
#define SMEM_SZ (NSTAGE * STAGE_BYTES)          // 108544

// ---------------- scratch -------------------------------------------------
__device__ float g_scores[BSQ * NE];
__device__ int   g_idx[NE * NK];
__device__ float g_gate[NE * NK];
__device__ __align__(256) __half g_h1h[(size_t)NE * NK * DFF];   // 128MB h1 (fp16)
__device__ __align__(256) __half g_Ah[(size_t)NE * NK * HID];    // 32MB gathered tokens
__device__ __align__(256) __half g_w1h[(size_t)NE * HID * DFF];  // 64MB w1 fp16
__device__ __align__(256) __half g_w2h[(size_t)NE * DFF * HID];  // 64MB w2 fp16

// ---------------- helpers ---------------------------------------------------
__device__ __forceinline__ uint32_t smem_u32(const void* p) {
    uint32_t a;
    asm("{ .reg .u64 t; cvta.to.shared.u64 t, %1; cvt.u32.u64 %0, t; }" : "=r"(a) : "l"(p));
    return a;
}
__device__ __forceinline__ void cp16(uint32_t dst, const void* src) {
    asm volatile("cp.async.cg.shared.global [%0], [%1], 16;" :: "r"(dst), "l"(src));
}
__device__ __forceinline__ void cp_commit() {
    asm volatile("cp.async.commit_group;" ::: "memory");
}
__device__ __forceinline__ void cp_wait2() {
    asm volatile("cp.async.wait_group 2;" ::: "memory");
}
__device__ __forceinline__ void ldsm4(uint32_t* r, uint32_t addr) {
    asm volatile("ldmatrix.sync.aligned.m8n8.x4.shared.b16 {%0,%1,%2,%3}, [%4];"
                 : "=r"(r[0]), "=r"(r[1]), "=r"(r[2]), "=r"(r[3]) : "r"(addr));
}
__device__ __forceinline__ void ldsm4t(uint32_t* r, uint32_t addr) {
    asm volatile("ldmatrix.sync.aligned.m8n8.x4.trans.shared.b16 {%0,%1,%2,%3}, [%4];"
                 : "=r"(r[0]), "=r"(r[1]), "=r"(r[2]), "=r"(r[3]) : "r"(addr));
}
__device__ __forceinline__ void mma_f16(float* d, const uint32_t* a, const uint32_t* b) {
    asm volatile("mma.sync.aligned.m16n8k16.row.col.f32.f16.f16.f32 "
                 "{%0,%1,%2,%3}, {%4,%5,%6,%7}, {%8,%9}, {%0,%1,%2,%3};"
                 : "+f"(d[0]), "+f"(d[1]), "+f"(d[2]), "+f"(d[3])
                 : "r"(a[0]), "r"(a[1]), "r"(a[2]), "r"(a[3]), "r"(b[0]), "r"(b[1]));
}

// ---------------- router ---------------------------------------------------
__global__ void router_kernel(const float* __restrict__ x,
                              const float* __restrict__ rw,
                              const float* __restrict__ rb) {
    __shared__ float srw[NE][HID];
    __shared__ float srb[NE];
    const int tid = threadIdx.x;
    for (int i = tid; i < HID * NE; i += 256) {
        int h = i >> 3, e = i & 7;
        srw[e][h] = rw[i];
    }
    if (tid < NE) srb[tid] = rb[tid];
    __syncthreads();

    const int w = tid >> 5, lane = tid & 31;
    const int t = blockIdx.x * 8 + w;
    const float* xr = x + (size_t)t * HID;
    float acc[NE];
#pragma unroll
    for (int e = 0; e < NE; e++) acc[e] = 0.f;
    for (int h = lane; h < HID; h += 32) {
        float xv = xr[h];
#pragma unroll
        for (int e = 0; e < NE; e++) acc[e] = fmaf(xv, srw[e][h], acc[e]);
    }
#pragma unroll
    for (int e = 0; e < NE; e++) {
#pragma unroll
        for (int off = 16; off > 0; off >>= 1)
            acc[e] += __shfl_down_sync(0xffffffffu, acc[e], off);
    }
    if (lane == 0) {
        float m = -1e30f;
#pragma unroll
        for (int e = 0; e < NE; e++) { acc[e] += srb[e]; m = fmaxf(m, acc[e]); }
        float s = 0.f;
#pragma unroll
        for (int e = 0; e < NE; e++) { acc[e] = expf(acc[e] - m); s += acc[e]; }
        float inv = 1.f / s;
#pragma unroll
        for (int e = 0; e < NE; e++) g_scores[(size_t)t * NE + e] = acc[e] * inv;
    }
}

// ---------------- top-K per expert -----------------------------------------
__global__ void topk_kernel() {
    const int e = blockIdx.x;
    const int tid = threadIdx.x;
    __shared__ int sg[1024];
    __shared__ int se[1024];
    __shared__ int red;

    unsigned v[8];
#pragma unroll
    for (int j = 0; j < 8; j++) {
        int i = tid * 8 + j;
        v[j] = __float_as_uint(g_scores[(size_t)i * NE + e]);
    }
    if (tid == 0) red = 0;
    __syncthreads();

    unsigned prefix = 0;
    int kr = NK;
    for (int bit = 31; bit >= 0; --bit) {
        unsigned want = (prefix >> bit) | 1u;
        int local = 0;
#pragma unroll
        for (int j = 0; j < 8; j++) local += ((v[j] >> bit) == want);
#pragma unroll
        for (int off = 16; off > 0; off >>= 1)
            local += __shfl_down_sync(0xffffffffu, local, off);
        if ((tid & 31) == 0) atomicAdd(&red, local);
        __syncthreads();
        int cnt = red;
        __syncthreads();
        if (tid == 0) red = 0;
        if (cnt >= kr) prefix |= (1u << bit); else kr -= cnt;
        __syncthreads();
    }
    const unsigned thr = prefix;

    int cg = 0, ce = 0;
#pragma unroll
    for (int j = 0; j < 8; j++) { cg += (v[j] > thr); ce += (v[j] == thr); }
    sg[tid] = cg; se[tid] = ce;
    __syncthreads();
    for (int d = 1; d < 1024; d <<= 1) {
        int a = (tid >= d) ? sg[tid - d] : 0;
        int b = (tid >= d) ? se[tid - d] : 0;
        __syncthreads();
        sg[tid] += a; se[tid] += b;
        __syncthreads();
    }
    const int C = sg[1023];
    int pg = sg[tid] - cg;
    int pe = se[tid] - ce;
    const int need = NK - C;
#pragma unroll
    for (int j = 0; j < 8; j++) {
        int tok = tid * 8 + j;
        if (v[j] > thr) {
            g_idx[e * NK + pg] = tok;
            g_gate[e * NK + pg] = __uint_as_float(v[j]);
            pg++;
        } else if (v[j] == thr) {
            if (pe < need) {
                int pos = C + pe;
                g_idx[e * NK + pos] = tok;
                g_gate[e * NK + pos] = __uint_as_float(v[j]);
            }
            pe++;
        }
    }
}

// ---------------- pre-passes ------------------------------------------------
// fp16 gather: g_Ah[row] = (half)x[g_idx[row]]
__global__ void gather_kernel(const float* __restrict__ x) {
    const int row = blockIdx.x;
    const int tok = g_idx[row];
    const float4* s = (const float4*)(x + (size_t)tok * HID);
    float4 v = s[threadIdx.x];
    __half2* d = (__half2*)(g_Ah + (size_t)row * HID) + threadIdx.x * 2;
    d[0] = __floats2half2_rn(v.x, v.y);
    d[1] = __floats2half2_rn(v.z, v.w);
}

// fp32 -> fp16 conversion of both weight tensors
__global__ void cvt_w_kernel(const float* __restrict__ w1, const float* __restrict__ w2) {
    const size_t n4 = (size_t)NE * HID * DFF / 4;
    const size_t stride = (size_t)gridDim.x * blockDim.x;
    for (size_t i = (size_t)blockIdx.x * blockDim.x + threadIdx.x; i < n4; i += stride) {
        float4 a = ((const float4*)w1)[i];
        ((__half2*)g_w1h)[2 * i]     = __floats2half2_rn(a.x, a.y);
        ((__half2*)g_w1h)[2 * i + 1] = __floats2half2_rn(a.z, a.w);
        float4 b = ((const float4*)w2)[i];
        ((__half2*)g_w2h)[2 * i]     = __floats2half2_rn(b.x, b.y);
        ((__half2*)g_w2h)[2 * i + 1] = __floats2half2_rn(b.z, b.w);
    }
}

// ---------------- fp16 mma mainloop -----------------------------------------
// A: BM x K halves (K-contig) at aG; B: [K][Nld] halves (N-contig) at bG.
__device__ __forceinline__ void load_stage(uint32_t sb, int buf, int tid,
                                           const __half* aG, int K,
                                           const __half* bG, int Nld, int k0) {
    const uint32_t baseA = sb + buf * STAGE_BYTES;
    const uint32_t baseB = baseA + A_BYTES_ST;
#pragma unroll
    for (int i = 0; i < 2; i++) {                       // A: 512 cp16 (128 rows x 64B)
        int id = tid + (i << 8);
        int r = id >> 2, c = id & 3;
        cp16(baseA + r * (RSA * 2) + c * 16, aG + (size_t)r * K + k0 + c * 8);
    }
#pragma unroll
    for (int i = 0; i < 4; i++) {                       // B: 1024 cp16 (32 rows x 512B)
        int id = tid + (i << 8);
        int kr = id >> 5, nc = id & 31;
        cp16(baseB + kr * (RSB * 2) + nc * 16, bG + (size_t)(k0 + kr) * Nld + nc * 8);
    }
}

__device__ __forceinline__ void gemm_mainloop(float acc[4][8][4], uint32_t sb, int tid,
                                              const __half* aG,
                                              const __half* bG, int Nld, int K) {
    const int wid = tid >> 5, lane = tid & 31;
    const int wm = wid & 1, wn = wid >> 1;              // 2 x 4 warp grid, 64x64 tiles
    const int lane15 = lane & 15, laneh = lane >> 4;
    const int KT = K / BK;
    // ldmatrix lane base offsets (bytes)
    const uint32_t aLane = (uint32_t)(wm * 64 + lane15) * (RSA * 2) + laneh * 16;
    const uint32_t bLane = (uint32_t)lane15 * (RSB * 2) + wn * 128 + laneh * 16;

#pragma unroll
    for (int mt = 0; mt < 4; mt++)
#pragma unroll
        for (int nt = 0; nt < 8; nt++)
#pragma unroll
            for (int q = 0; q < 4; q++) acc[mt][nt][q] = 0.f;

    for (int s = 0; s < NSTAGE - 1; s++) {
        load_stage(sb, s, tid, aG, K, bG, Nld, s * BK);
        cp_commit();
    }

    for (int k = 0; k < KT; k++) {
        const int buf = k & (NSTAGE - 1);
        cp_wait2();
        __syncthreads();

        const uint32_t bufA = sb + buf * STAGE_BYTES + aLane;
        const uint32_t bufB = sb + buf * STAGE_BYTES + A_BYTES_ST + bLane;
#pragma unroll
        for (int kk = 0; kk < 2; kk++) {
            uint32_t aF[4][4], bF[4][4];
#pragma unroll
            for (int mt = 0; mt < 4; mt++)
                ldsm4(aF[mt], bufA + mt * (16 * RSA * 2) + kk * 32);
#pragma unroll
            for (int nt = 0; nt < 4; nt++)
                ldsm4t(bF[nt], bufB + kk * (16 * RSB * 2) + nt * 32);
#pragma unroll
            for (int mt = 0; mt < 4; mt++)
#pragma unroll
                for (int nt = 0; nt < 4; nt++) {
                    mma_f16(acc[mt][2 * nt],     aF[mt], &bF[nt][0]);
                    mma_f16(acc[mt][2 * nt + 1], aF[mt], &bF[nt][2]);
                }
        }
        __syncthreads();

        const int pf = k + NSTAGE - 1;
        if (pf < KT) load_stage(sb, pf & (NSTAGE - 1), tid, aG, K, bG, Nld, pf * BK);
        cp_commit();   // empty group when no prefetch keeps wait_group invariant
    }
}

// ---------------- GEMM1: g_h1h = half(relu(g_Ah @ w1h + b1)) ----------------
__global__ __launch_bounds__(256, 1)
void gemm1_tc(const float* __restrict__ b1) {
    extern __shared__ char smem[];
    const uint32_t sb = smem_u32(smem);
    const int tid = threadIdx.x;
    const int e = blockIdx.z, n0 = blockIdx.x * BN, m0 = blockIdx.y * BM;

    const __half* aG = g_Ah + (size_t)(e * NK + m0) * HID;
    const __half* bG = g_w1h + (size_t)e * HID * DFF + n0;
    float acc[4][8][4];
    gemm_mainloop(acc, sb, tid, aG, bG, DFF, HID);

    const int wid = tid >> 5, lane = tid & 31;
    const int wm = wid & 1, wn = wid >> 1;
    const int g = lane >> 2, c = lane & 3;
#pragma unroll
    for (int mt = 0; mt < 4; mt++) {
        const int r0 = m0 + wm * 64 + mt * 16 + g;
#pragma unroll
        for (int nt = 0; nt < 8; nt++) {
            const int cc = n0 + wn * 64 + nt * 8 + 2 * c;
            const float bx = b1[(size_t)e * DFF + cc];
            const float by = b1[(size_t)e * DFF + cc + 1];
            __half2 v0 = __floats2half2_rn(fmaxf(acc[mt][nt][0] + bx, 0.f),
                                           fmaxf(acc[mt][nt][1] + by, 0.f));
            __half2 v1 = __floats2half2_rn(fmaxf(acc[mt][nt][2] + bx, 0.f),
                                           fmaxf(acc[mt][nt][3] + by, 0.f));
            *(__half2*)&g_h1h[(size_t)(e * NK + r0) * DFF + cc] = v0;
            *(__half2*)&g_h1h[(size_t)(e * NK + r0 + 8) * DFF + cc] = v1;
        }
    }
}

// ---------------- GEMM2: out += gate * (g_h1h @ w2h + b2) -------------------
__global__ __launch_bounds__(256, 1)
void gemm2_tc(const float* __restrict__ b2, float* __restrict__ out) {
    extern __shared__ char smem[];
    const uint32_t sb = smem_u32(smem);
    const int tid = threadIdx.x;
    const int e = blockIdx.z, n0 = blockIdx.x * BN, m0 = blockIdx.y * BM;

    const __half* aG = g_h1h + (size_t)(e * NK + m0) * DFF;
    const __half* bG = g_w2h + (size_t)e * DFF * HID + n0;
    float acc[4][8][4];
    gemm_mainloop(acc, sb, tid, aG, bG, HID, DFF);

    const int wid = tid >> 5, lane = tid & 31;
    const int wm = wid & 1, wn = wid >> 1;
    const int g = lane >> 2, c = lane & 3;
#pragma unroll
    for (int mt = 0; mt < 4; mt++) {
        const int r0 = m0 + wm * 64 + mt * 16 + g;
        const int tok0 = g_idx[e * NK + r0];
        const int tok1 = g_idx[e * NK + r0 + 8];
        const float g0 = g_gate[e * NK + r0];
        const float g1 = g_gate[e * NK + r0 + 8];
#pragma unroll
        for (int nt = 0; nt < 8; nt++) {
            const int cc = n0 + wn * 64 + nt * 8 + 2 * c;
            const float bx = b2[(size_t)e * HID + cc];
            const float by = b2[(size_t)e * HID + cc + 1];
            atomicAdd(out + (size_t)tok0 * HID + cc,     (acc[mt][nt][0] + bx) * g0);
            atomicAdd(out + (size_t)tok0 * HID + cc + 1, (acc[mt][nt][1] + by) * g0);
            atomicAdd(out + (size_t)tok1 * HID + cc,     (acc[mt][nt][2] + bx) * g1);
            atomicAdd(out + (size_t)tok1 * HID + cc + 1, (acc[mt][nt][3] + by) * g1);
        }
    }
}

// ---------------- launch ----------------------------------------------------
extern "C" void kernel_launch(void* const* d_in, const int* in_sizes, int n_in,
                              void* d_out, int out_size) {
    const float* x  = (const float*)d_in[0];
    const float* rw = (const float*)d_in[1];
    const float* rb = (const float*)d_in[2];
    const float* w1 = (const float*)d_in[3];
    const float* b1 = (const float*)d_in[4];
    const float* w2 = (const float*)d_in[5];
    const float* b2 = (const float*)d_in[6];
    float* out = (float*)d_out;

    cudaFuncSetAttribute(gemm1_tc, cudaFuncAttributeMaxDynamicSharedMemorySize, SMEM_SZ);
    cudaFuncSetAttribute(gemm2_tc, cudaFuncAttributeMaxDynamicSharedMemorySize, SMEM_SZ);

    cvt_w_kernel<<<2048, 256>>>(w1, w2);
    router_kernel<<<BSQ / 8, 256>>>(x, rw, rb);
    topk_kernel<<<NE, 1024>>>();
    gather_kernel<<<NE * NK, 256>>>(x);
    cudaMemsetAsync(d_out, 0, (size_t)out_size * sizeof(float), 0);
    gemm1_tc<<<dim3(DFF / BN, NK / BM, NE), 256, SMEM_SZ>>>(b1);
    gemm2_tc<<<dim3(HID / BN, NK / BM, NE), 256, SMEM_SZ>>>(b2, out);
}

// round 7
// speedup vs baseline: 7.2072x; 2.0368x over previous
#include <cuda_runtime.h>
#include <cuda_fp16.h>
#include <cstdint>
#include <math.h>

#define BSQ 8192   // B*S tokens
#define HID 1024
#define DFF 4096
#define NE  8
#define NK  2048

// GEMM tiling: CTA 128x128x64, 8 warps of 64x32, fp16 m16n8k16, 2 CTAs/SM
#define BM 128
#define BN 128
#define BK 64
#define NSTAGE 3
#define RSA 72                           // A row stride (halves): 144B rows, ldsm conflict-free
#define RSB 136                          // B row stride (halves): 272B rows, conflict-free
#define A_BYTES_ST (BM * RSA * 2)        // 18432
#define B_BYTES_ST (BK * RSB * 2)        // 17408
#define STAGE_BYTES (A_BYTES_ST + B_BYTES_ST)   // 35840
#define SMEM_SZ (NSTAGE * STAGE_BYTES)          // 107520 -> 2 CTAs/SM

// ---------------- scratch -------------------------------------------------
__device__ float g_scores[BSQ * NE];
__device__ int   g_idx[NE * NK];
__device__ float g_gate[NE * NK];
__device__ __align__(256) __half g_h1h[(size_t)NE * NK * DFF];   // 128MB h1 (fp16)
__device__ __align__(256) __half g_Ah[(size_t)NE * NK * HID];    // 32MB gathered tokens
__device__ __align__(256) __half g_w1h[(size_t)NE * HID * DFF];  // 64MB w1 fp16
__device__ __align__(256) __half g_w2h[(size_t)NE * DFF * HID];  // 64MB w2 fp16

// ---------------- helpers ---------------------------------------------------
__device__ __forceinline__ uint32_t smem_u32(const void* p) {
    uint32_t a;
    asm("{ .reg .u64 t; cvta.to.shared.u64 t, %1; cvt.u32.u64 %0, t; }" : "=r"(a) : "l"(p));
    return a;
}
__device__ __forceinline__ void cp16(uint32_t dst, const void* src) {
    asm volatile("cp.async.cg.shared.global [%0], [%1], 16;" :: "r"(dst), "l"(src));
}
__device__ __forceinline__ void cp_commit() {
    asm volatile("cp.async.commit_group;" ::: "memory");
}
__device__ __forceinline__ void cp_wait1() {
    asm volatile("cp.async.wait_group 1;" ::: "memory");
}
__device__ __forceinline__ void ldsm4(uint32_t* r, uint32_t addr) {
    asm volatile("ldmatrix.sync.aligned.m8n8.x4.shared.b16 {%0,%1,%2,%3}, [%4];"
                 : "=r"(r[0]), "=r"(r[1]), "=r"(r[2]), "=r"(r[3]) : "r"(addr));
}
__device__ __forceinline__ void ldsm4t(uint32_t* r, uint32_t addr) {
    asm volatile("ldmatrix.sync.aligned.m8n8.x4.trans.shared.b16 {%0,%1,%2,%3}, [%4];"
                 : "=r"(r[0]), "=r"(r[1]), "=r"(r[2]), "=r"(r[3]) : "r"(addr));
}
__device__ __forceinline__ void mma_f16(float* d, const uint32_t* a, const uint32_t* b) {
    asm volatile("mma.sync.aligned.m16n8k16.row.col.f32.f16.f16.f32 "
                 "{%0,%1,%2,%3}, {%4,%5,%6,%7}, {%8,%9}, {%0,%1,%2,%3};"
                 : "+f"(d[0]), "+f"(d[1]), "+f"(d[2]), "+f"(d[3])
                 : "r"(a[0]), "r"(a[1]), "r"(a[2]), "r"(a[3]), "r"(b[0]), "r"(b[1]));
}

// ---------------- router ---------------------------------------------------
__global__ void router_kernel(const float* __restrict__ x,
                              const float* __restrict__ rw,
                              const float* __restrict__ rb) {
    __shared__ float srw[NE][HID];
    __shared__ float srb[NE];
    const int tid = threadIdx.x;
    for (int i = tid; i < HID * NE; i += 256) {
        int h = i >> 3, e = i & 7;
        srw[e][h] = rw[i];
    }
    if (tid < NE) srb[tid] = rb[tid];
    __syncthreads();

    const int w = tid >> 5, lane = tid & 31;
    const int t = blockIdx.x * 8 + w;
    const float* xr = x + (size_t)t * HID;
    float acc[NE];
#pragma unroll
    for (int e = 0; e < NE; e++) acc[e] = 0.f;
    for (int h = lane; h < HID; h += 32) {
        float xv = xr[h];
#pragma unroll
        for (int e = 0; e < NE; e++) acc[e] = fmaf(xv, srw[e][h], acc[e]);
    }
#pragma unroll
    for (int e = 0; e < NE; e++) {
#pragma unroll
        for (int off = 16; off > 0; off >>= 1)
            acc[e] += __shfl_down_sync(0xffffffffu, acc[e], off);
    }
    if (lane == 0) {
        float m = -1e30f;
#pragma unroll
        for (int e = 0; e < NE; e++) { acc[e] += srb[e]; m = fmaxf(m, acc[e]); }
        float s = 0.f;
#pragma unroll
        for (int e = 0; e < NE; e++) { acc[e] = expf(acc[e] - m); s += acc[e]; }
        float inv = 1.f / s;
#pragma unroll
        for (int e = 0; e < NE; e++) g_scores[(size_t)t * NE + e] = acc[e] * inv;
    }
}

// ---------------- top-K per expert -----------------------------------------
__global__ void topk_kernel() {
    const int e = blockIdx.x;
    const int tid = threadIdx.x;
    __shared__ int sg[1024];
    __shared__ int se[1024];
    __shared__ int red;

    unsigned v[8];
#pragma unroll
    for (int j = 0; j < 8; j++) {
        int i = tid * 8 + j;
        v[j] = __float_as_uint(g_scores[(size_t)i * NE + e]);
    }
    if (tid == 0) red = 0;
    __syncthreads();

    unsigned prefix = 0;
    int kr = NK;
    for (int bit = 31; bit >= 0; --bit) {
        unsigned want = (prefix >> bit) | 1u;
        int local = 0;
#pragma unroll
        for (int j = 0; j < 8; j++) local += ((v[j] >> bit) == want);
#pragma unroll
        for (int off = 16; off > 0; off >>= 1)
            local += __shfl_down_sync(0xffffffffu, local, off);
        if ((tid & 31) == 0) atomicAdd(&red, local);
        __syncthreads();
        int cnt = red;
        __syncthreads();
        if (tid == 0) red = 0;
        if (cnt >= kr) prefix |= (1u << bit); else kr -= cnt;
        __syncthreads();
    }
    const unsigned thr = prefix;

    int cg = 0, ce = 0;
#pragma unroll
    for (int j = 0; j < 8; j++) { cg += (v[j] > thr); ce += (v[j] == thr); }
    sg[tid] = cg; se[tid] = ce;
    __syncthreads();
    for (int d = 1; d < 1024; d <<= 1) {
        int a = (tid >= d) ? sg[tid - d] : 0;
        int b = (tid >= d) ? se[tid - d] : 0;
        __syncthreads();
        sg[tid] += a; se[tid] += b;
        __syncthreads();
    }
    const int C = sg[1023];
    int pg = sg[tid] - cg;
    int pe = se[tid] - ce;
    const int need = NK - C;
#pragma unroll
    for (int j = 0; j < 8; j++) {
        int tok = tid * 8 + j;
        if (v[j] > thr) {
            g_idx[e * NK + pg] = tok;
            g_gate[e * NK + pg] = __uint_as_float(v[j]);
            pg++;
        } else if (v[j] == thr) {
            if (pe < need) {
                int pos = C + pe;
                g_idx[e * NK + pos] = tok;
                g_gate[e * NK + pos] = __uint_as_float(v[j]);
            }
            pe++;
        }
    }
}

// ---------------- pre-passes ------------------------------------------------
__global__ void gather_kernel(const float* __restrict__ x) {
    const int row = blockIdx.x;
    const int tok = g_idx[row];
    const float4* s = (const float4*)(x + (size_t)tok * HID);
    float4 v = s[threadIdx.x];
    __half2* d = (__half2*)(g_Ah + (size_t)row * HID) + threadIdx.x * 2;
    d[0] = __floats2half2_rn(v.x, v.y);
    d[1] = __floats2half2_rn(v.z, v.w);
}

__global__ void cvt_w_kernel(const float* __restrict__ w1, const float* __restrict__ w2) {
    const size_t n4 = (size_t)NE * HID * DFF / 4;
    const size_t stride = (size_t)gridDim.x * blockDim.x;
    for (size_t i = (size_t)blockIdx.x * blockDim.x + threadIdx.x; i < n4; i += stride) {
        float4 a = ((const float4*)w1)[i];
        ((__half2*)g_w1h)[2 * i]     = __floats2half2_rn(a.x, a.y);
        ((__half2*)g_w1h)[2 * i + 1] = __floats2half2_rn(a.z, a.w);
        float4 b = ((const float4*)w2)[i];
        ((__half2*)g_w2h)[2 * i]     = __floats2half2_rn(b.x, b.y);
        ((__half2*)g_w2h)[2 * i + 1] = __floats2half2_rn(b.z, b.w);
    }
}

// ---------------- fp16 mma mainloop -----------------------------------------
// A: BM x K halves (K-contig) at aG; B: [K][Nld] halves (N-contig) at bG.
__device__ __forceinline__ void load_stage(uint32_t sb, int buf, int tid,
                                           const __half* aG, int K,
                                           const __half* bG, int Nld, int k0) {
    const uint32_t baseA = sb + buf * STAGE_BYTES;
    const uint32_t baseB = baseA + A_BYTES_ST;
#pragma unroll
    for (int i = 0; i < 4; i++) {                       // A: 1024 cp16 (128 rows x 128B)
        int id = tid + (i << 8);
        int r = id >> 3, c = id & 7;
        cp16(baseA + r * (RSA * 2) + c * 16, aG + (size_t)r * K + k0 + c * 8);
    }
#pragma unroll
    for (int i = 0; i < 4; i++) {                       // B: 1024 cp16 (64 rows x 256B)
        int id = tid + (i << 8);
        int kr = id >> 4, nc = id & 15;
        cp16(baseB + kr * (RSB * 2) + nc * 16, bG + (size_t)(k0 + kr) * Nld + nc * 8);
    }
}

__device__ __forceinline__ void gemm_mainloop(float acc[4][4][4], uint32_t sb, int tid,
                                              const __half* aG,
                                              const __half* bG, int Nld, int K) {
    const int wid = tid >> 5, lane = tid & 31;
    const int wm = wid & 1, wn = wid >> 1;              // 2 x 4 warp grid, 64x32 tiles
    const int lane15 = lane & 15, laneh = lane >> 4;
    const int KT = K / BK;
    const uint32_t aLane = (uint32_t)(wm * 64 + lane15) * (RSA * 2) + laneh * 16;
    const uint32_t bLane = (uint32_t)lane15 * (RSB * 2) + wn * 64 + laneh * 16;

#pragma unroll
    for (int mt = 0; mt < 4; mt++)
#pragma unroll
        for (int nt = 0; nt < 4; nt++)
#pragma unroll
            for (int q = 0; q < 4; q++) acc[mt][nt][q] = 0.f;

    for (int s = 0; s < NSTAGE - 1; s++) {
        load_stage(sb, s, tid, aG, K, bG, Nld, s * BK);
        cp_commit();
    }

    for (int k = 0; k < KT; k++) {
        const int buf = k % NSTAGE;
        cp_wait1();
        __syncthreads();   // single barrier per iter: also fences prior-iter reads
                           // before this iter's loads overwrite buf (k+2)%3

        const uint32_t bufA = sb + buf * STAGE_BYTES + aLane;
        const uint32_t bufB = sb + buf * STAGE_BYTES + A_BYTES_ST + bLane;
#pragma unroll
        for (int kk = 0; kk < 4; kk++) {
            uint32_t aF[4][4], bF[2][4];
#pragma unroll
            for (int mt = 0; mt < 4; mt++)
                ldsm4(aF[mt], bufA + mt * (16 * RSA * 2) + kk * 32);
#pragma unroll
            for (int np = 0; np < 2; np++)
                ldsm4t(bF[np], bufB + kk * (16 * RSB * 2) + np * 32);
#pragma unroll
            for (int mt = 0; mt < 4; mt++)
#pragma unroll
                for (int np = 0; np < 2; np++) {
                    mma_f16(acc[mt][2 * np],     aF[mt], &bF[np][0]);
                    mma_f16(acc[mt][2 * np + 1], aF[mt], &bF[np][2]);
                }
        }

        const int pf = k + NSTAGE - 1;
        if (pf < KT) load_stage(sb, pf % NSTAGE, tid, aG, K, bG, Nld, pf * BK);
        cp_commit();   // empty group when no prefetch keeps wait_group invariant
    }
}

// ---------------- GEMM1: g_h1h = half(relu(g_Ah @ w1h + b1)) ----------------
__global__ __launch_bounds__(256, 2)
void gemm1_tc(const float* __restrict__ b1) {
    extern __shared__ char smem[];
    const uint32_t sb = smem_u32(smem);
    const int tid = threadIdx.x;
    const int e = blockIdx.z, n0 = blockIdx.x * BN, m0 = blockIdx.y * BM;

    const __half* aG = g_Ah + (size_t)(e * NK + m0) * HID;
    const __half* bG = g_w1h + (size_t)e * HID * DFF + n0;
    float acc[4][4][4];
    gemm_mainloop(acc, sb, tid, aG, bG, DFF, HID);

    const int wid = tid >> 5, lane = tid & 31;
    const int wm = wid & 1, wn = wid >> 1;
    const int g = lane >> 2, c = lane & 3;
#pragma unroll
    for (int mt = 0; mt < 4; mt++) {
        const int r0 = m0 + wm * 64 + mt * 16 + g;
#pragma unroll
        for (int nt = 0; nt < 4; nt++) {
            const int cc = n0 + wn * 32 + nt * 8 + 2 * c;
            const float bx = b1[(size_t)e * DFF + cc];
            const float by = b1[(size_t)e * DFF + cc + 1];
            __half2 v0 = __floats2half2_rn(fmaxf(acc[mt][nt][0] + bx, 0.f),
                                           fmaxf(acc[mt][nt][1] + by, 0.f));
            __half2 v1 = __floats2half2_rn(fmaxf(acc[mt][nt][2] + bx, 0.f),
                                           fmaxf(acc[mt][nt][3] + by, 0.f));
            *(__half2*)&g_h1h[(size_t)(e * NK + r0) * DFF + cc] = v0;
            *(__half2*)&g_h1h[(size_t)(e * NK + r0 + 8) * DFF + cc] = v1;
        }
    }
}

// ---------------- GEMM2: out += gate * (g_h1h @ w2h + b2) -------------------
__global__ __launch_bounds__(256, 2)
void gemm2_tc(const float* __restrict__ b2, float* __restrict__ out) {
    extern __shared__ char smem[];
    const uint32_t sb = smem_u32(smem);
    const int tid = threadIdx.x;
    const int e = blockIdx.z, n0 = blockIdx.x * BN, m0 = blockIdx.y * BM;

    const __half* aG = g_h1h + (size_t)(e * NK + m0) * DFF;
    const __half* bG = g_w2h + (size_t)e * DFF * HID + n0;
    float acc[4][4][4];
    gemm_mainloop(acc, sb, tid, aG, bG, HID, DFF);

    const int wid = tid >> 5, lane = tid & 31;
    const int wm = wid & 1, wn = wid >> 1;
    const int g = lane >> 2, c = lane & 3;
#pragma unroll
    for (int mt = 0; mt < 4; mt++) {
        const int r0 = m0 + wm * 64 + mt * 16 + g;
        const int tok0 = g_idx[e * NK + r0];
        const int tok1 = g_idx[e * NK + r0 + 8];
        const float g0 = g_gate[e * NK + r0];
        const float g1 = g_gate[e * NK + r0 + 8];
#pragma unroll
        for (int nt = 0; nt < 4; nt++) {
            const int cc = n0 + wn * 32 + nt * 8 + 2 * c;
            const float bx = b2[(size_t)e * HID + cc];
            const float by = b2[(size_t)e * HID + cc + 1];
            atomicAdd(out + (size_t)tok0 * HID + cc,     (acc[mt][nt][0] + bx) * g0);
            atomicAdd(out + (size_t)tok0 * HID + cc + 1, (acc[mt][nt][1] + by) * g0);
            atomicAdd(out + (size_t)tok1 * HID + cc,     (acc[mt][nt][2] + bx) * g1);
            atomicAdd(out + (size_t)tok1 * HID + cc + 1, (acc[mt][nt][3] + by) * g1);
        }
    }
}

// ---------------- launch ----------------------------------------------------
extern "C" void kernel_launch(void* const* d_in, const int* in_sizes, int n_in,
                              void* d_out, int out_size) {
    const float* x  = (const float*)d_in[0];
    const float* rw = (const float*)d_in[1];
    const float* rb = (const float*)d_in[2];
    const float* w1 = (const float*)d_in[3];
    const float* b1 = (const float*)d_in[4];
    const float* w2 = (const float*)d_in[5];
    const float* b2 = (const float*)d_in[6];
    float* out = (float*)d_out;

    cudaFuncSetAttribute(gemm1_tc, cudaFuncAttributeMaxDynamicSharedMemorySize, SMEM_SZ);
    cudaFuncSetAttribute(gemm2_tc, cudaFuncAttributeMaxDynamicSharedMemorySize, SMEM_SZ);

    cvt_w_kernel<<<2048, 256>>>(w1, w2);
    router_kernel<<<BSQ / 8, 256>>>(x, rw, rb);
    topk_kernel<<<NE, 1024>>>();
    gather_kernel<<<NE * NK, 256>>>(x);
    cudaMemsetAsync(d_out, 0, (size_t)out_size * sizeof(float), 0);
    gemm1_tc<<<dim3(DFF / BN, NK / BM, NE), 256, SMEM_SZ>>>(b1);
    gemm2_tc<<<dim3(HID / BN, NK / BM, NE), 256, SMEM_SZ>>>(b2, out);
}